// round 1
// baseline (speedup 1.0000x reference)
#include <cuda_runtime.h>
#include <cuda_bf16.h>
#include <cstdint>

#define HW 65536
#define EPSN 1e-12f

typedef unsigned long long u64;

// ---------------- scratch (static device globals; no allocation) ----------------
__device__ float g_qm [33554432];   // [8][64][65536]  qm = conv1x1(degra)*conv1x1(x)
__device__ float g_kvm[67108864];   // [8][128][65536] kvm = conv1x1(y, kv_w)
__device__ float g_v  [33554432];   // [8][64][65536]  v after dwconv
__device__ float g_gram[8192];      // [8][4][16][16]  sum q_c * k_d (unnormalized)
__device__ float g_qss[512];        // [8][64] sum q^2
__device__ float g_kss[512];        // [8][64] sum k^2
__device__ float g_M  [32768];      // [8][64][64] fused proj*attn matrix

// ---------------- f32x2 helpers ----------------
__device__ __forceinline__ u64 pk2(float lo, float hi){
    u64 r; asm("mov.b64 %0, {%1, %2};" : "=l"(r) : "f"(lo), "f"(hi)); return r;
}
__device__ __forceinline__ void upk2(u64 v, float& lo, float& hi){
    asm("mov.b64 {%0, %1}, %2;" : "=f"(lo), "=f"(hi) : "l"(v));
}
__device__ __forceinline__ u64 ffma2(u64 a, u64 b, u64 c){
    u64 d; asm("fma.rn.f32x2 %0, %1, %2, %3;" : "=l"(d) : "l"(a), "l"(b), "l"(c)); return d;
}
__device__ __forceinline__ u64 fmul2p(u64 a, u64 b){
    u64 d; asm("mul.rn.f32x2 %0, %1, %2;" : "=l"(d) : "l"(a), "l"(b)); return d;
}
__device__ __forceinline__ void fma_bcast(u64 (&acc)[2], float w, const u64 (&p)[2]){
    u64 wp = pk2(w, w);
    acc[0] = ffma2(wp, p[0], acc[0]);
    acc[1] = ffma2(wp, p[1], acc[1]);
}

// ---------------- K0: zero the accumulators (every replay) ----------------
__global__ void k0_init(){
    int i = blockIdx.x * 256 + threadIdx.x;
    if (i < 8192) g_gram[i] = 0.f;
    if (i < 512){ g_qss[i] = 0.f; g_kss[i] = 0.f; }
}

// ---------------- K1: the three conv1x1 GEMMs, fused ----------------
// block = 128 pixels of one batch; 256 threads = 32 px-lanes x 8 ch-rows.
// smem: input tiles 3x[64][128] (96KB) + weight buffer 8192 floats (32KB) = 128KB dynamic.
__global__ void __launch_bounds__(256, 1) k1_conv1x1(
    const float* __restrict__ dg, const float* __restrict__ xin, const float* __restrict__ yin,
    const float* __restrict__ q1w, const float* __restrict__ q2w, const float* __restrict__ kvw)
{
    extern __shared__ float sm[];
    float* sD = sm;
    float* sX = sm + 8192;
    float* sY = sm + 16384;
    float* sW = sm + 24576;           // 8192 floats
    const int b    = blockIdx.x >> 9;
    const int base = (blockIdx.x & 511) << 7;
    const int tid  = threadIdx.x;
    const int tx   = tid & 31, ty = tid >> 5;
    const size_t inoff = (size_t)b * 64 * HW + base;

    for (int i = tid; i < 2048; i += 256){
        const int c = i >> 5, p = (i & 31) << 2;
        *(float4*)(sD + c*128 + p) = *(const float4*)(dg  + inoff + (size_t)c*HW + p);
        *(float4*)(sX + c*128 + p) = *(const float4*)(xin + inoff + (size_t)c*HW + p);
        *(float4*)(sY + c*128 + p) = *(const float4*)(yin + inoff + (size_t)c*HW + p);
    }
    for (int i = tid; i < 1024; i += 256){
        *(float4*)(sW +        (i<<2)) = *(const float4*)(q1w + (i<<2));
        *(float4*)(sW + 4096 + (i<<2)) = *(const float4*)(q2w + (i<<2));
    }
    __syncthreads();

    // ---- q path: q1 = W1*degra, q2 = W2*x, qm = q1*q2 ----
    u64 a1[8][2], a2[8][2];
    #pragma unroll
    for (int i = 0; i < 8; ++i){ a1[i][0]=a1[i][1]=a2[i][0]=a2[i][1]=0ull; }

    for (int k0 = 0; k0 < 64; k0 += 4){
        u64 dP[4][2], xP[4][2];
        #pragma unroll
        for (int kk = 0; kk < 4; ++kk){
            float4 d4 = *(float4*)(sD + (k0+kk)*128 + (tx<<2));
            dP[kk][0] = pk2(d4.x, d4.y); dP[kk][1] = pk2(d4.z, d4.w);
            float4 x4 = *(float4*)(sX + (k0+kk)*128 + (tx<<2));
            xP[kk][0] = pk2(x4.x, x4.y); xP[kk][1] = pk2(x4.z, x4.w);
        }
        #pragma unroll
        for (int i = 0; i < 8; ++i){
            const int o = ty + (i<<3);
            float4 w1 = *(float4*)(sW +        o*64 + k0);
            float4 w2 = *(float4*)(sW + 4096 + o*64 + k0);
            fma_bcast(a1[i], w1.x, dP[0]); fma_bcast(a1[i], w1.y, dP[1]);
            fma_bcast(a1[i], w1.z, dP[2]); fma_bcast(a1[i], w1.w, dP[3]);
            fma_bcast(a2[i], w2.x, xP[0]); fma_bcast(a2[i], w2.y, xP[1]);
            fma_bcast(a2[i], w2.z, xP[2]); fma_bcast(a2[i], w2.w, xP[3]);
        }
    }
    #pragma unroll
    for (int i = 0; i < 8; ++i){
        const int o = ty + (i<<3);
        u64 m0 = fmul2p(a1[i][0], a2[i][0]);
        u64 m1 = fmul2p(a1[i][1], a2[i][1]);
        float4 r; upk2(m0, r.x, r.y); upk2(m1, r.z, r.w);
        *(float4*)(g_qm + ((size_t)(b*64 + o))*HW + base + (tx<<2)) = r;
    }
    __syncthreads();

    // ---- kv path: kvm = Wkv * y (128 outputs) ----
    for (int i = tid; i < 2048; i += 256)
        *(float4*)(sW + (i<<2)) = *(const float4*)(kvw + (i<<2));
    __syncthreads();

    u64 av[16][2];
    #pragma unroll
    for (int i = 0; i < 16; ++i){ av[i][0]=av[i][1]=0ull; }

    for (int k0 = 0; k0 < 64; k0 += 4){
        u64 yP[4][2];
        #pragma unroll
        for (int kk = 0; kk < 4; ++kk){
            float4 y4 = *(float4*)(sY + (k0+kk)*128 + (tx<<2));
            yP[kk][0] = pk2(y4.x, y4.y); yP[kk][1] = pk2(y4.z, y4.w);
        }
        #pragma unroll
        for (int i = 0; i < 16; ++i){
            const int o = ty + (i<<3);
            float4 w = *(float4*)(sW + o*64 + k0);
            fma_bcast(av[i], w.x, yP[0]); fma_bcast(av[i], w.y, yP[1]);
            fma_bcast(av[i], w.z, yP[2]); fma_bcast(av[i], w.w, yP[3]);
        }
    }
    #pragma unroll
    for (int i = 0; i < 16; ++i){
        const int o = ty + (i<<3);
        float4 r; upk2(av[i][0], r.x, r.y); upk2(av[i][1], r.z, r.w);
        *(float4*)(g_kvm + ((size_t)(b*128 + o))*HW + base + (tx<<2)) = r;
    }
}

// ---------------- K2: depthwise 3x3 + gram/norm reductions + v store ----------------
__device__ __forceinline__ float4 dw3(const float* __restrict__ src, int yy, int xx,
                                      const float* __restrict__ w9)
{
    float w[9];
    #pragma unroll
    for (int i = 0; i < 9; ++i) w[i] = __ldg(w9 + i);
    float4 r = make_float4(0.f, 0.f, 0.f, 0.f);
    #pragma unroll
    for (int ky = 0; ky < 3; ++ky){
        int ys = yy + ky - 1;
        if (ys < 0 || ys > 255) continue;
        const float* row = src + ys*256 + xx;
        float  v0 = (xx > 0)   ? __ldg(row - 1) : 0.f;
        float4 c4 = __ldg((const float4*)row);
        float  v5 = (xx < 252) ? __ldg(row + 4) : 0.f;
        float w0 = w[ky*3], w1 = w[ky*3+1], w2 = w[ky*3+2];
        r.x += w0*v0   + w1*c4.x + w2*c4.y;
        r.y += w0*c4.x + w1*c4.y + w2*c4.z;
        r.z += w0*c4.y + w1*c4.z + w2*c4.w;
        r.w += w0*c4.z + w1*c4.w + w2*v5;
    }
    return r;
}

__device__ __forceinline__ float bflo(unsigned u){ return __int_as_float((int)(u << 16)); }
__device__ __forceinline__ float bfhi(unsigned u){ return __int_as_float((int)(u & 0xffff0000u)); }

// block = (b, head, 4-row tile). 256 threads = 4 rows x 64 quads.
// dynamic smem: sQ/sK bf16 [1024][16] (64KB) + 32 floats partials.
__global__ void __launch_bounds__(256, 1) k2_dw(
    const float* __restrict__ qdw, const float* __restrict__ kvdw)
{
    extern __shared__ char sm2[];
    __nv_bfloat16* sQ = (__nv_bfloat16*)sm2;         // 16384 elems
    __nv_bfloat16* sK = sQ + 16384;                  // 16384 elems
    float* sSS = (float*)(sm2 + 65536);              // 32 floats

    const int b = blockIdx.z, h = blockIdx.y, yt = blockIdx.x;
    const int tid = threadIdx.x;
    const int ry = tid >> 6, xq = tid & 63, xx = xq << 2;
    const int yy = yt*4 + ry;
    const int lane = tid & 31;

    if (tid < 32) sSS[tid] = 0.f;
    __syncthreads();

    for (int c = 0; c < 16; ++c){
        // q
        {
            const float* src = g_qm + ((size_t)(b*64 + h*16 + c))*HW;
            float4 r = dw3(src, yy, xx, qdw + (h*16 + c)*9);
            float s = r.x*r.x + r.y*r.y + r.z*r.z + r.w*r.w;
            #pragma unroll
            for (int o = 16; o; o >>= 1) s += __shfl_xor_sync(0xffffffffu, s, o);
            if (lane == 0) atomicAdd(&sSS[c], s);
            int pb = (ry*256 + xx)*16 + c;
            sQ[pb     ] = __float2bfloat16(r.x);
            sQ[pb + 16] = __float2bfloat16(r.y);
            sQ[pb + 32] = __float2bfloat16(r.z);
            sQ[pb + 48] = __float2bfloat16(r.w);
        }
        // k
        {
            const float* src = g_kvm + ((size_t)(b*128 + h*16 + c))*HW;
            float4 r = dw3(src, yy, xx, kvdw + (h*16 + c)*9);
            float s = r.x*r.x + r.y*r.y + r.z*r.z + r.w*r.w;
            #pragma unroll
            for (int o = 16; o; o >>= 1) s += __shfl_xor_sync(0xffffffffu, s, o);
            if (lane == 0) atomicAdd(&sSS[16 + c], s);
            int pb = (ry*256 + xx)*16 + c;
            sK[pb     ] = __float2bfloat16(r.x);
            sK[pb + 16] = __float2bfloat16(r.y);
            sK[pb + 32] = __float2bfloat16(r.z);
            sK[pb + 48] = __float2bfloat16(r.w);
        }
        // v -> gmem
        {
            const float* src = g_kvm + ((size_t)(b*128 + 64 + h*16 + c))*HW;
            float4 r = dw3(src, yy, xx, kvdw + (64 + h*16 + c)*9);
            *(float4*)(g_v + ((size_t)(b*64 + h*16 + c))*HW + yy*256 + xx) = r;
        }
    }
    __syncthreads();
    if (tid < 16)       atomicAdd(g_qss + b*64 + h*16 + tid,        sSS[tid]);
    else if (tid < 32)  atomicAdd(g_kss + b*64 + h*16 + (tid - 16), sSS[tid]);

    // ---- gram: 16 groups x (4x4 thread grid), each thread a 4x4 (i,j) tile ----
    const int g  = tid >> 4;
    const int it = (tid >> 2) & 3;
    const int jt = tid & 3;
    float acc[4][4];
    #pragma unroll
    for (int a = 0; a < 4; ++a)
        #pragma unroll
        for (int b2 = 0; b2 < 4; ++b2) acc[a][b2] = 0.f;

    for (int p = g*64; p < g*64 + 64; ++p){
        uint2 qu = *(const uint2*)(sQ + p*16 + it*4);
        uint2 ku = *(const uint2*)(sK + p*16 + jt*4);
        float qv[4], kv[4];
        qv[0] = bflo(qu.x); qv[1] = bfhi(qu.x); qv[2] = bflo(qu.y); qv[3] = bfhi(qu.y);
        kv[0] = bflo(ku.x); kv[1] = bfhi(ku.x); kv[2] = bflo(ku.y); kv[3] = bfhi(ku.y);
        #pragma unroll
        for (int a = 0; a < 4; ++a)
            #pragma unroll
            for (int b2 = 0; b2 < 4; ++b2) acc[a][b2] += qv[a]*kv[b2];
    }
    __syncthreads();
    float* sGr = (float*)sm2;   // 4096 floats, overlays sQ (done reading it)
    #pragma unroll
    for (int a = 0; a < 4; ++a)
        #pragma unroll
        for (int b2 = 0; b2 < 4; ++b2)
            sGr[g*256 + (it*4 + a)*16 + (jt*4 + b2)] = acc[a][b2];
    __syncthreads();
    float tot = 0.f;
    #pragma unroll
    for (int gg = 0; gg < 16; ++gg) tot += sGr[gg*256 + tid];
    atomicAdd(g_gram + (b*4 + h)*256 + tid, tot);
}

// ---------------- K3: softmax + fold proj into per-batch 64x64 matrix M ----------------
__global__ void __launch_bounds__(256) k3_attn(
    const float* __restrict__ pjw, const float* __restrict__ temp)
{
    __shared__ float sA[1024];          // attn [64 rows][16]
    __shared__ float snq[64], snk[64];
    const int b = blockIdx.x, tid = threadIdx.x;
    if (tid < 64){
        snq[tid] = fmaxf(sqrtf(g_qss[b*64 + tid]), EPSN);
        snk[tid] = fmaxf(sqrtf(g_kss[b*64 + tid]), EPSN);
    }
    __syncthreads();
    if (tid < 64){
        const int h = tid >> 4;
        const float t = __ldg(temp + h);
        const float inq = t / snq[tid];
        const float* gr = g_gram + (b*4 + h)*256 + (tid & 15)*16;
        float l[16]; float mx = -1e30f;
        #pragma unroll
        for (int d = 0; d < 16; ++d){ l[d] = gr[d] * inq / snk[h*16 + d]; mx = fmaxf(mx, l[d]); }
        float ssum = 0.f;
        #pragma unroll
        for (int d = 0; d < 16; ++d){ l[d] = __expf(l[d] - mx); ssum += l[d]; }
        const float inv = 1.f / ssum;
        #pragma unroll
        for (int d = 0; d < 16; ++d) sA[tid*16 + d] = l[d] * inv;
    }
    __syncthreads();
    for (int idx = tid; idx < 4096; idx += 256){
        const int o = idx >> 6, cd = idx & 63, h = cd >> 4, d = cd & 15;
        float s = 0.f;
        #pragma unroll
        for (int ci = 0; ci < 16; ++ci)
            s += __ldg(pjw + o*64 + h*16 + ci) * sA[(h*16 + ci)*16 + d];
        g_M[b*4096 + idx] = s;
    }
}

// ---------------- K4: out = M[b] @ v  (fused attn@v + proj) ----------------
__global__ void __launch_bounds__(256, 1) k4_out(float* __restrict__ out)
{
    __shared__ float sV[8192];   // [64][128]
    __shared__ float sM[4096];   // [64][64]
    const int b    = blockIdx.x >> 9;
    const int base = (blockIdx.x & 511) << 7;
    const int tid  = threadIdx.x;
    const int tx   = tid & 31, ty = tid >> 5;
    const size_t voff = (size_t)b * 64 * HW + base;

    for (int i = tid; i < 2048; i += 256){
        const int c = i >> 5, p = (i & 31) << 2;
        *(float4*)(sV + c*128 + p) = *(const float4*)(g_v + voff + (size_t)c*HW + p);
    }
    for (int i = tid; i < 1024; i += 256)
        *(float4*)(sM + (i<<2)) = *(const float4*)(g_M + b*4096 + (i<<2));
    __syncthreads();

    u64 acc[8][2];
    #pragma unroll
    for (int i = 0; i < 8; ++i){ acc[i][0] = acc[i][1] = 0ull; }

    for (int k0 = 0; k0 < 64; k0 += 4){
        u64 vP[4][2];
        #pragma unroll
        for (int kk = 0; kk < 4; ++kk){
            float4 v4 = *(float4*)(sV + (k0+kk)*128 + (tx<<2));
            vP[kk][0] = pk2(v4.x, v4.y); vP[kk][1] = pk2(v4.z, v4.w);
        }
        #pragma unroll
        for (int i = 0; i < 8; ++i){
            float4 w = *(float4*)(sM + (ty + (i<<3))*64 + k0);
            fma_bcast(acc[i], w.x, vP[0]); fma_bcast(acc[i], w.y, vP[1]);
            fma_bcast(acc[i], w.z, vP[2]); fma_bcast(acc[i], w.w, vP[3]);
        }
    }
    #pragma unroll
    for (int i = 0; i < 8; ++i){
        const int o = ty + (i<<3);
        float4 r; upk2(acc[i][0], r.x, r.y); upk2(acc[i][1], r.z, r.w);
        *(float4*)(out + ((size_t)(b*64 + o))*HW + base + (tx<<2)) = r;
    }
}

// ---------------- launch ----------------
extern "C" void kernel_launch(void* const* d_in, const int* in_sizes, int n_in,
                              void* d_out, int out_size)
{
    (void)in_sizes; (void)n_in; (void)out_size;
    const float* dg   = (const float*)d_in[0];
    const float* xin  = (const float*)d_in[1];
    const float* yin  = (const float*)d_in[2];
    const float* q1w  = (const float*)d_in[3];
    const float* q2w  = (const float*)d_in[4];
    const float* qdw  = (const float*)d_in[5];
    const float* kvw  = (const float*)d_in[6];
    const float* kvdw = (const float*)d_in[7];
    const float* pjw  = (const float*)d_in[8];
    const float* temp = (const float*)d_in[9];
    float* out = (float*)d_out;

    cudaFuncSetAttribute(k1_conv1x1, cudaFuncAttributeMaxDynamicSharedMemorySize, 131072);
    cudaFuncSetAttribute(k2_dw,      cudaFuncAttributeMaxDynamicSharedMemorySize, 67584);

    k0_init<<<32, 256>>>();
    k1_conv1x1<<<4096, 256, 131072>>>(dg, xin, yin, q1w, q2w, kvw);
    k2_dw<<<dim3(64, 4, 8), 256, 67584>>>(qdw, kvdw);
    k3_attn<<<8, 256>>>(pjw, temp);
    k4_out<<<4096, 256>>>(out);
}

// round 2
// speedup vs baseline: 1.2627x; 1.2627x over previous
#include <cuda_runtime.h>
#include <cuda_bf16.h>
#include <cstdint>

#define HW 65536
#define EPSN 1e-12f

typedef unsigned long long u64;

// ---------------- scratch (static device globals; no allocation) ----------------
__device__ float g_qm [33554432];   // [8][64][65536]  qm = conv1x1(degra)*conv1x1(x)
__device__ float g_kvm[67108864];   // [8][128][65536] kvm = conv1x1(y, kv_w)
__device__ float g_v  [33554432];   // [8][64][65536]  v after dwconv
__device__ float g_gram[8192];      // [8][4][16][16]
__device__ float g_qss[512];        // [8][64]
__device__ float g_kss[512];        // [8][64]
__device__ float g_M  [32768];      // [8][64][64] fused proj*attn

// ---------------- f32x2 helpers ----------------
__device__ __forceinline__ u64 pk2(float lo, float hi){
    u64 r; asm("mov.b64 %0, {%1, %2};" : "=l"(r) : "f"(lo), "f"(hi)); return r;
}
__device__ __forceinline__ void upk2(u64 v, float& lo, float& hi){
    asm("mov.b64 {%0, %1}, %2;" : "=f"(lo), "=f"(hi) : "l"(v));
}
__device__ __forceinline__ u64 ffma2(u64 a, u64 b, u64 c){
    u64 d; asm("fma.rn.f32x2 %0, %1, %2, %3;" : "=l"(d) : "l"(a), "l"(b), "l"(c)); return d;
}
__device__ __forceinline__ u64 fmul2p(u64 a, u64 b){
    u64 d; asm("mul.rn.f32x2 %0, %1, %2;" : "=l"(d) : "l"(a), "l"(b)); return d;
}
__device__ __forceinline__ void fma_bcast(u64 (&acc)[2], float w, const u64 (&p)[2]){
    u64 wp = pk2(w, w);
    acc[0] = ffma2(wp, p[0], acc[0]);
    acc[1] = ffma2(wp, p[1], acc[1]);
}

// ---------------- cp.async helpers ----------------
__device__ __forceinline__ void cpa16(void* smem, const void* g){
    unsigned s = (unsigned)__cvta_generic_to_shared(smem);
    asm volatile("cp.async.cg.shared.global [%0], [%1], 16;" :: "r"(s), "l"(g));
}
__device__ __forceinline__ void cpa_commit(){ asm volatile("cp.async.commit_group;"); }
__device__ __forceinline__ void cpa_wait1(){ asm volatile("cp.async.wait_group 1;"); }

// ---------------- K0: zero the accumulators (every replay) ----------------
__global__ void k0_init(){
    int i = blockIdx.x * 256 + threadIdx.x;
    if (i < 8192) g_gram[i] = 0.f;
    if (i < 512){ g_qss[i] = 0.f; g_kss[i] = 0.f; }
}

#define NTILES 4096   // 128-px tiles over 8 batches x 65536 px

// ---------------- K1a: q path (2 GEMMs), persistent + double-buffered ----------------
// smem: sW1 4096f + sW2 4096f (32KB) + 2 stages x (sD 8192f + sX 8192f) (128KB) = 160KB
__global__ void __launch_bounds__(256, 1) k1a_q(
    const float* __restrict__ dg, const float* __restrict__ xin,
    const float* __restrict__ q1w, const float* __restrict__ q2w)
{
    extern __shared__ float sm[];
    float* sW1 = sm;
    float* sW2 = sm + 4096;
    float* buf = sm + 8192;          // stage s: sD = buf+s*16384, sX = sD+8192
    const int tid = threadIdx.x, tx = tid & 31, ty = tid >> 5;

    for (int i = tid; i < 1024; i += 256){
        *(float4*)(sW1 + (i<<2)) = *(const float4*)(q1w + (i<<2));
        *(float4*)(sW2 + (i<<2)) = *(const float4*)(q2w + (i<<2));
    }

    auto issue = [&](int t, int s){
        if (t < NTILES){
            const int b = t >> 9; const size_t base = (size_t)(t & 511) << 7;
            const float* gd = dg  + (size_t)b*64*HW + base;
            const float* gx = xin + (size_t)b*64*HW + base;
            float* sD = buf + s*16384; float* sX = sD + 8192;
            #pragma unroll
            for (int i = tid; i < 2048; i += 256){
                const int c = i >> 5, off = (i & 31) << 2;
                cpa16(sD + c*128 + off, gd + (size_t)c*HW + off);
                cpa16(sX + c*128 + off, gx + (size_t)c*HW + off);
            }
        }
        cpa_commit();
    };

    int s = 0;
    issue(blockIdx.x, 0);
    for (int t = blockIdx.x; t < NTILES; t += gridDim.x){
        issue(t + gridDim.x, s ^ 1);
        cpa_wait1();
        __syncthreads();

        const float* sD = buf + s*16384; const float* sX = sD + 8192;
        u64 a1[8][2], a2[8][2];
        #pragma unroll
        for (int i = 0; i < 8; ++i){ a1[i][0]=a1[i][1]=a2[i][0]=a2[i][1]=0ull; }

        #pragma unroll 4
        for (int k0 = 0; k0 < 64; k0 += 4){
            u64 dP[4][2], xP[4][2];
            #pragma unroll
            for (int kk = 0; kk < 4; ++kk){
                float4 d4 = *(const float4*)(sD + (k0+kk)*128 + (tx<<2));
                dP[kk][0] = pk2(d4.x, d4.y); dP[kk][1] = pk2(d4.z, d4.w);
                float4 x4 = *(const float4*)(sX + (k0+kk)*128 + (tx<<2));
                xP[kk][0] = pk2(x4.x, x4.y); xP[kk][1] = pk2(x4.z, x4.w);
            }
            #pragma unroll
            for (int i = 0; i < 8; ++i){
                const int o = ty + (i<<3);
                float4 w1 = *(const float4*)(sW1 + o*64 + k0);
                float4 w2 = *(const float4*)(sW2 + o*64 + k0);
                fma_bcast(a1[i], w1.x, dP[0]); fma_bcast(a1[i], w1.y, dP[1]);
                fma_bcast(a1[i], w1.z, dP[2]); fma_bcast(a1[i], w1.w, dP[3]);
                fma_bcast(a2[i], w2.x, xP[0]); fma_bcast(a2[i], w2.y, xP[1]);
                fma_bcast(a2[i], w2.z, xP[2]); fma_bcast(a2[i], w2.w, xP[3]);
            }
        }
        const int b = t >> 9; const size_t base = (size_t)(t & 511) << 7;
        #pragma unroll
        for (int i = 0; i < 8; ++i){
            const int o = ty + (i<<3);
            u64 m0 = fmul2p(a1[i][0], a2[i][0]);
            u64 m1 = fmul2p(a1[i][1], a2[i][1]);
            float4 r; upk2(m0, r.x, r.y); upk2(m1, r.z, r.w);
            *(float4*)(g_qm + ((size_t)(b*64 + o))*HW + base + (tx<<2)) = r;
        }
        __syncthreads();
        s ^= 1;
    }
}

// ---------------- K1b: kv GEMM (128 outs), persistent + double-buffered ----------------
// smem: sW 8192f (32KB) + 2 stages x 8192f (64KB) = 96KB -> 2 CTAs/SM
__global__ void __launch_bounds__(256, 2) k1b_kv(
    const float* __restrict__ yin, const float* __restrict__ kvw)
{
    extern __shared__ float sm[];
    float* sW  = sm;                 // 8192
    float* buf = sm + 8192;          // stage s: buf + s*8192
    const int tid = threadIdx.x, tx = tid & 31, ty = tid >> 5;

    for (int i = tid; i < 2048; i += 256)
        *(float4*)(sW + (i<<2)) = *(const float4*)(kvw + (i<<2));

    auto issue = [&](int t, int s){
        if (t < NTILES){
            const int b = t >> 9; const size_t base = (size_t)(t & 511) << 7;
            const float* gy = yin + (size_t)b*64*HW + base;
            float* sY = buf + s*8192;
            #pragma unroll
            for (int i = tid; i < 2048; i += 256){
                const int c = i >> 5, off = (i & 31) << 2;
                cpa16(sY + c*128 + off, gy + (size_t)c*HW + off);
            }
        }
        cpa_commit();
    };

    int s = 0;
    issue(blockIdx.x, 0);
    for (int t = blockIdx.x; t < NTILES; t += gridDim.x){
        issue(t + gridDim.x, s ^ 1);
        cpa_wait1();
        __syncthreads();

        const float* sY = buf + s*8192;
        u64 av[16][2];
        #pragma unroll
        for (int i = 0; i < 16; ++i){ av[i][0]=av[i][1]=0ull; }

        #pragma unroll 4
        for (int k0 = 0; k0 < 64; k0 += 4){
            u64 yP[4][2];
            #pragma unroll
            for (int kk = 0; kk < 4; ++kk){
                float4 y4 = *(const float4*)(sY + (k0+kk)*128 + (tx<<2));
                yP[kk][0] = pk2(y4.x, y4.y); yP[kk][1] = pk2(y4.z, y4.w);
            }
            #pragma unroll
            for (int i = 0; i < 16; ++i){
                const int o = ty + (i<<3);
                float4 w = *(const float4*)(sW + o*64 + k0);
                fma_bcast(av[i], w.x, yP[0]); fma_bcast(av[i], w.y, yP[1]);
                fma_bcast(av[i], w.z, yP[2]); fma_bcast(av[i], w.w, yP[3]);
            }
        }
        const int b = t >> 9; const size_t base = (size_t)(t & 511) << 7;
        #pragma unroll
        for (int i = 0; i < 16; ++i){
            const int o = ty + (i<<3);
            float4 r; upk2(av[i][0], r.x, r.y); upk2(av[i][1], r.z, r.w);
            *(float4*)(g_kvm + ((size_t)(b*128 + o))*HW + base + (tx<<2)) = r;
        }
        __syncthreads();
        s ^= 1;
    }
}

// ---------------- K2: depthwise 3x3 + gram/norm reductions + v store ----------------
__device__ __forceinline__ float4 dw3(const float* __restrict__ src, int yy, int xx,
                                      const float* __restrict__ w9)
{
    float w[9];
    #pragma unroll
    for (int i = 0; i < 9; ++i) w[i] = __ldg(w9 + i);
    float4 r = make_float4(0.f, 0.f, 0.f, 0.f);
    #pragma unroll
    for (int ky = 0; ky < 3; ++ky){
        int ys = yy + ky - 1;
        if (ys < 0 || ys > 255) continue;
        const float* row = src + ys*256 + xx;
        float  v0 = (xx > 0)   ? __ldg(row - 1) : 0.f;
        float4 c4 = __ldg((const float4*)row);
        float  v5 = (xx < 252) ? __ldg(row + 4) : 0.f;
        float w0 = w[ky*3], w1 = w[ky*3+1], w2 = w[ky*3+2];
        r.x += w0*v0   + w1*c4.x + w2*c4.y;
        r.y += w0*c4.x + w1*c4.y + w2*c4.z;
        r.z += w0*c4.y + w1*c4.z + w2*c4.w;
        r.w += w0*c4.z + w1*c4.w + w2*v5;
    }
    return r;
}

__device__ __forceinline__ float bflo(unsigned u){ return __int_as_float((int)(u << 16)); }
__device__ __forceinline__ float bfhi(unsigned u){ return __int_as_float((int)(u & 0xffff0000u)); }

__global__ void __launch_bounds__(256, 1) k2_dw(
    const float* __restrict__ qdw, const float* __restrict__ kvdw)
{
    extern __shared__ char sm2[];
    __nv_bfloat16* sQ = (__nv_bfloat16*)sm2;         // 16384 elems
    __nv_bfloat16* sK = sQ + 16384;                  // 16384 elems
    float* sSS = (float*)(sm2 + 65536);              // 32 floats

    const int b = blockIdx.z, h = blockIdx.y, yt = blockIdx.x;
    const int tid = threadIdx.x;
    const int ry = tid >> 6, xq = tid & 63, xx = xq << 2;
    const int yy = yt*4 + ry;
    const int lane = tid & 31;

    if (tid < 32) sSS[tid] = 0.f;
    __syncthreads();

    for (int c = 0; c < 16; ++c){
        {
            const float* src = g_qm + ((size_t)(b*64 + h*16 + c))*HW;
            float4 r = dw3(src, yy, xx, qdw + (h*16 + c)*9);
            float s = r.x*r.x + r.y*r.y + r.z*r.z + r.w*r.w;
            #pragma unroll
            for (int o = 16; o; o >>= 1) s += __shfl_xor_sync(0xffffffffu, s, o);
            if (lane == 0) atomicAdd(&sSS[c], s);
            int pb = (ry*256 + xx)*16 + c;
            sQ[pb     ] = __float2bfloat16(r.x);
            sQ[pb + 16] = __float2bfloat16(r.y);
            sQ[pb + 32] = __float2bfloat16(r.z);
            sQ[pb + 48] = __float2bfloat16(r.w);
        }
        {
            const float* src = g_kvm + ((size_t)(b*128 + h*16 + c))*HW;
            float4 r = dw3(src, yy, xx, kvdw + (h*16 + c)*9);
            float s = r.x*r.x + r.y*r.y + r.z*r.z + r.w*r.w;
            #pragma unroll
            for (int o = 16; o; o >>= 1) s += __shfl_xor_sync(0xffffffffu, s, o);
            if (lane == 0) atomicAdd(&sSS[16 + c], s);
            int pb = (ry*256 + xx)*16 + c;
            sK[pb     ] = __float2bfloat16(r.x);
            sK[pb + 16] = __float2bfloat16(r.y);
            sK[pb + 32] = __float2bfloat16(r.z);
            sK[pb + 48] = __float2bfloat16(r.w);
        }
        {
            const float* src = g_kvm + ((size_t)(b*128 + 64 + h*16 + c))*HW;
            float4 r = dw3(src, yy, xx, kvdw + (64 + h*16 + c)*9);
            *(float4*)(g_v + ((size_t)(b*64 + h*16 + c))*HW + yy*256 + xx) = r;
        }
    }
    __syncthreads();
    if (tid < 16)       atomicAdd(g_qss + b*64 + h*16 + tid,        sSS[tid]);
    else if (tid < 32)  atomicAdd(g_kss + b*64 + h*16 + (tid - 16), sSS[tid]);

    const int g  = tid >> 4;
    const int it = (tid >> 2) & 3;
    const int jt = tid & 3;
    float acc[4][4];
    #pragma unroll
    for (int a = 0; a < 4; ++a)
        #pragma unroll
        for (int b2 = 0; b2 < 4; ++b2) acc[a][b2] = 0.f;

    for (int p = g*64; p < g*64 + 64; ++p){
        uint2 qu = *(const uint2*)(sQ + p*16 + it*4);
        uint2 ku = *(const uint2*)(sK + p*16 + jt*4);
        float qv[4], kv[4];
        qv[0] = bflo(qu.x); qv[1] = bfhi(qu.x); qv[2] = bflo(qu.y); qv[3] = bfhi(qu.y);
        kv[0] = bflo(ku.x); kv[1] = bfhi(ku.x); kv[2] = bflo(ku.y); kv[3] = bfhi(ku.y);
        #pragma unroll
        for (int a = 0; a < 4; ++a)
            #pragma unroll
            for (int b2 = 0; b2 < 4; ++b2) acc[a][b2] += qv[a]*kv[b2];
    }
    __syncthreads();
    float* sGr = (float*)sm2;
    #pragma unroll
    for (int a = 0; a < 4; ++a)
        #pragma unroll
        for (int b2 = 0; b2 < 4; ++b2)
            sGr[g*256 + (it*4 + a)*16 + (jt*4 + b2)] = acc[a][b2];
    __syncthreads();
    float tot = 0.f;
    #pragma unroll
    for (int gg = 0; gg < 16; ++gg) tot += sGr[gg*256 + tid];
    atomicAdd(g_gram + (b*4 + h)*256 + tid, tot);
}

// ---------------- K3: softmax + fold proj into per-batch 64x64 matrix M ----------------
__global__ void __launch_bounds__(256) k3_attn(
    const float* __restrict__ pjw, const float* __restrict__ temp)
{
    __shared__ float sA[1024];
    __shared__ float snq[64], snk[64];
    const int b = blockIdx.x, tid = threadIdx.x;
    if (tid < 64){
        snq[tid] = fmaxf(sqrtf(g_qss[b*64 + tid]), EPSN);
        snk[tid] = fmaxf(sqrtf(g_kss[b*64 + tid]), EPSN);
    }
    __syncthreads();
    if (tid < 64){
        const int h = tid >> 4;
        const float t = __ldg(temp + h);
        const float inq = t / snq[tid];
        const float* gr = g_gram + (b*4 + h)*256 + (tid & 15)*16;
        float l[16]; float mx = -1e30f;
        #pragma unroll
        for (int d = 0; d < 16; ++d){ l[d] = gr[d] * inq / snk[h*16 + d]; mx = fmaxf(mx, l[d]); }
        float ssum = 0.f;
        #pragma unroll
        for (int d = 0; d < 16; ++d){ l[d] = __expf(l[d] - mx); ssum += l[d]; }
        const float inv = 1.f / ssum;
        #pragma unroll
        for (int d = 0; d < 16; ++d) sA[tid*16 + d] = l[d] * inv;
    }
    __syncthreads();
    for (int idx = tid; idx < 4096; idx += 256){
        const int o = idx >> 6, cd = idx & 63, h = cd >> 4, d = cd & 15;
        float s = 0.f;
        #pragma unroll
        for (int ci = 0; ci < 16; ++ci)
            s += __ldg(pjw + o*64 + h*16 + ci) * sA[(h*16 + ci)*16 + d];
        g_M[b*4096 + idx] = s;
    }
}

// ---------------- K4: out = M[b] @ v, persistent + double-buffered ----------------
// smem: 2 stages x (sV 8192f + sM 4096f) = 96KB -> 2 CTAs/SM
__global__ void __launch_bounds__(256, 2) k4_out(float* __restrict__ out)
{
    extern __shared__ float sm[];
    float* buf = sm;                 // stage s: sV = buf + s*12288, sM = sV + 8192
    const int tid = threadIdx.x, tx = tid & 31, ty = tid >> 5;

    auto issue = [&](int t, int s){
        if (t < NTILES){
            const int b = t >> 9; const size_t base = (size_t)(t & 511) << 7;
            const float* gv = g_v + (size_t)b*64*HW + base;
            const float* gm = g_M + b*4096;
            float* sV = buf + s*12288; float* sM = sV + 8192;
            #pragma unroll
            for (int i = tid; i < 2048; i += 256){
                const int c = i >> 5, off = (i & 31) << 2;
                cpa16(sV + c*128 + off, gv + (size_t)c*HW + off);
            }
            #pragma unroll
            for (int i = tid; i < 1024; i += 256)
                cpa16(sM + (i<<2), gm + (i<<2));
        }
        cpa_commit();
    };

    int s = 0;
    issue(blockIdx.x, 0);
    for (int t = blockIdx.x; t < NTILES; t += gridDim.x){
        issue(t + gridDim.x, s ^ 1);
        cpa_wait1();
        __syncthreads();

        const float* sV = buf + s*12288; const float* sM = sV + 8192;
        u64 acc[8][2];
        #pragma unroll
        for (int i = 0; i < 8; ++i){ acc[i][0] = acc[i][1] = 0ull; }

        #pragma unroll 4
        for (int k0 = 0; k0 < 64; k0 += 4){
            u64 vP[4][2];
            #pragma unroll
            for (int kk = 0; kk < 4; ++kk){
                float4 v4 = *(const float4*)(sV + (k0+kk)*128 + (tx<<2));
                vP[kk][0] = pk2(v4.x, v4.y); vP[kk][1] = pk2(v4.z, v4.w);
            }
            #pragma unroll
            for (int i = 0; i < 8; ++i){
                float4 w = *(const float4*)(sM + (ty + (i<<3))*64 + k0);
                fma_bcast(acc[i], w.x, vP[0]); fma_bcast(acc[i], w.y, vP[1]);
                fma_bcast(acc[i], w.z, vP[2]); fma_bcast(acc[i], w.w, vP[3]);
            }
        }
        const int b = t >> 9; const size_t base = (size_t)(t & 511) << 7;
        #pragma unroll
        for (int i = 0; i < 8; ++i){
            const int o = ty + (i<<3);
            float4 r; upk2(acc[i][0], r.x, r.y); upk2(acc[i][1], r.z, r.w);
            *(float4*)(out + ((size_t)(b*64 + o))*HW + base + (tx<<2)) = r;
        }
        __syncthreads();
        s ^= 1;
    }
}

// ---------------- launch ----------------
extern "C" void kernel_launch(void* const* d_in, const int* in_sizes, int n_in,
                              void* d_out, int out_size)
{
    (void)in_sizes; (void)n_in; (void)out_size;
    const float* dg   = (const float*)d_in[0];
    const float* xin  = (const float*)d_in[1];
    const float* yin  = (const float*)d_in[2];
    const float* q1w  = (const float*)d_in[3];
    const float* q2w  = (const float*)d_in[4];
    const float* qdw  = (const float*)d_in[5];
    const float* kvw  = (const float*)d_in[6];
    const float* kvdw = (const float*)d_in[7];
    const float* pjw  = (const float*)d_in[8];
    const float* temp = (const float*)d_in[9];
    float* out = (float*)d_out;

    cudaFuncSetAttribute(k1a_q,  cudaFuncAttributeMaxDynamicSharedMemorySize, 163840);
    cudaFuncSetAttribute(k1b_kv, cudaFuncAttributeMaxDynamicSharedMemorySize, 98304);
    cudaFuncSetAttribute(k2_dw,  cudaFuncAttributeMaxDynamicSharedMemorySize, 67584);
    cudaFuncSetAttribute(k4_out, cudaFuncAttributeMaxDynamicSharedMemorySize, 98304);

    k0_init<<<32, 256>>>();
    k1a_q <<<152, 256, 163840>>>(dg, xin, q1w, q2w);
    k1b_kv<<<304, 256,  98304>>>(yin, kvw);
    k2_dw <<<dim3(64, 4, 8), 256, 67584>>>(qdw, kvdw);
    k3_attn<<<8, 256>>>(pjw, temp);
    k4_out<<<304, 256,  98304>>>(out);
}

// round 3
// speedup vs baseline: 1.7454x; 1.3823x over previous
#include <cuda_runtime.h>
#include <cuda_bf16.h>
#include <cstdint>

#define HW 65536
#define EPSN 1e-12f

typedef unsigned long long u64;

// ---------------- scratch (static device globals; no allocation) ----------------
__device__ float g_qm [33554432];   // [8][64][65536]  qm = conv1x1(degra)*conv1x1(x)
__device__ float g_kvm[67108864];   // [8][128][65536] kvm = conv1x1(y, kv_w)
__device__ float g_v  [33554432];   // [8][64][65536]  v after dwconv
__device__ unsigned g_qb[16777216]; // [8][64][65536] bf16 q_dw (packed pairs)
__device__ unsigned g_kb[16777216]; // [8][64][65536] bf16 k_dw
__device__ float g_gram[8192];      // [8][4][16][16]
__device__ float g_qss[512];        // [8][64]
__device__ float g_kss[512];        // [8][64]
__device__ float g_M  [32768];      // [8][64][64] fused proj*attn

// ---------------- f32x2 helpers ----------------
__device__ __forceinline__ u64 pk2(float lo, float hi){
    u64 r; asm("mov.b64 %0, {%1, %2};" : "=l"(r) : "f"(lo), "f"(hi)); return r;
}
__device__ __forceinline__ void upk2(u64 v, float& lo, float& hi){
    asm("mov.b64 {%0, %1}, %2;" : "=f"(lo), "=f"(hi) : "l"(v));
}
__device__ __forceinline__ u64 ffma2(u64 a, u64 b, u64 c){
    u64 d; asm("fma.rn.f32x2 %0, %1, %2, %3;" : "=l"(d) : "l"(a), "l"(b), "l"(c)); return d;
}
__device__ __forceinline__ u64 fmul2p(u64 a, u64 b){
    u64 d; asm("mul.rn.f32x2 %0, %1, %2;" : "=l"(d) : "l"(a), "l"(b)); return d;
}
__device__ __forceinline__ void fma_bcast(u64 (&acc)[2], float w, const u64 (&p)[2]){
    u64 wp = pk2(w, w);
    acc[0] = ffma2(wp, p[0], acc[0]);
    acc[1] = ffma2(wp, p[1], acc[1]);
}

// ---------------- cp.async helpers ----------------
__device__ __forceinline__ void cpa16(void* smem, const void* g){
    unsigned s = (unsigned)__cvta_generic_to_shared(smem);
    asm volatile("cp.async.cg.shared.global [%0], [%1], 16;" :: "r"(s), "l"(g));
}
__device__ __forceinline__ void cpa_commit(){ asm volatile("cp.async.commit_group;"); }
__device__ __forceinline__ void cpa_wait1(){ asm volatile("cp.async.wait_group 1;"); }

// ---------------- K0: zero the accumulators (every replay) ----------------
__global__ void k0_init(){
    int i = blockIdx.x * 256 + threadIdx.x;
    if (i < 8192) g_gram[i] = 0.f;
    if (i < 512){ g_qss[i] = 0.f; g_kss[i] = 0.f; }
}

#define NTILES 4096   // 128-px tiles over 8 batches x 65536 px

// ---------------- K1a: q path (2 GEMMs), persistent + double-buffered ----------------
__global__ void __launch_bounds__(256, 1) k1a_q(
    const float* __restrict__ dg, const float* __restrict__ xin,
    const float* __restrict__ q1w, const float* __restrict__ q2w)
{
    extern __shared__ float sm[];
    float* sW1 = sm;
    float* sW2 = sm + 4096;
    float* buf = sm + 8192;
    const int tid = threadIdx.x, tx = tid & 31, ty = tid >> 5;

    for (int i = tid; i < 1024; i += 256){
        *(float4*)(sW1 + (i<<2)) = *(const float4*)(q1w + (i<<2));
        *(float4*)(sW2 + (i<<2)) = *(const float4*)(q2w + (i<<2));
    }

    auto issue = [&](int t, int s){
        if (t < NTILES){
            const int b = t >> 9; const size_t base = (size_t)(t & 511) << 7;
            const float* gd = dg  + (size_t)b*64*HW + base;
            const float* gx = xin + (size_t)b*64*HW + base;
            float* sD = buf + s*16384; float* sX = sD + 8192;
            #pragma unroll
            for (int i = tid; i < 2048; i += 256){
                const int c = i >> 5, off = (i & 31) << 2;
                cpa16(sD + c*128 + off, gd + (size_t)c*HW + off);
                cpa16(sX + c*128 + off, gx + (size_t)c*HW + off);
            }
        }
        cpa_commit();
    };

    int s = 0;
    issue(blockIdx.x, 0);
    for (int t = blockIdx.x; t < NTILES; t += gridDim.x){
        issue(t + gridDim.x, s ^ 1);
        cpa_wait1();
        __syncthreads();

        const float* sD = buf + s*16384; const float* sX = sD + 8192;
        u64 a1[8][2], a2[8][2];
        #pragma unroll
        for (int i = 0; i < 8; ++i){ a1[i][0]=a1[i][1]=a2[i][0]=a2[i][1]=0ull; }

        #pragma unroll 4
        for (int k0 = 0; k0 < 64; k0 += 4){
            u64 dP[4][2], xP[4][2];
            #pragma unroll
            for (int kk = 0; kk < 4; ++kk){
                float4 d4 = *(const float4*)(sD + (k0+kk)*128 + (tx<<2));
                dP[kk][0] = pk2(d4.x, d4.y); dP[kk][1] = pk2(d4.z, d4.w);
                float4 x4 = *(const float4*)(sX + (k0+kk)*128 + (tx<<2));
                xP[kk][0] = pk2(x4.x, x4.y); xP[kk][1] = pk2(x4.z, x4.w);
            }
            #pragma unroll
            for (int i = 0; i < 8; ++i){
                const int o = ty + (i<<3);
                float4 w1 = *(const float4*)(sW1 + o*64 + k0);
                float4 w2 = *(const float4*)(sW2 + o*64 + k0);
                fma_bcast(a1[i], w1.x, dP[0]); fma_bcast(a1[i], w1.y, dP[1]);
                fma_bcast(a1[i], w1.z, dP[2]); fma_bcast(a1[i], w1.w, dP[3]);
                fma_bcast(a2[i], w2.x, xP[0]); fma_bcast(a2[i], w2.y, xP[1]);
                fma_bcast(a2[i], w2.z, xP[2]); fma_bcast(a2[i], w2.w, xP[3]);
            }
        }
        const int b = t >> 9; const size_t base = (size_t)(t & 511) << 7;
        #pragma unroll
        for (int i = 0; i < 8; ++i){
            const int o = ty + (i<<3);
            u64 m0 = fmul2p(a1[i][0], a2[i][0]);
            u64 m1 = fmul2p(a1[i][1], a2[i][1]);
            float4 r; upk2(m0, r.x, r.y); upk2(m1, r.z, r.w);
            *(float4*)(g_qm + ((size_t)(b*64 + o))*HW + base + (tx<<2)) = r;
        }
        __syncthreads();
        s ^= 1;
    }
}

// ---------------- K1b: kv GEMM (128 outs), persistent + double-buffered ----------------
__global__ void __launch_bounds__(256, 2) k1b_kv(
    const float* __restrict__ yin, const float* __restrict__ kvw)
{
    extern __shared__ float sm[];
    float* sW  = sm;
    float* buf = sm + 8192;
    const int tid = threadIdx.x, tx = tid & 31, ty = tid >> 5;

    for (int i = tid; i < 2048; i += 256)
        *(float4*)(sW + (i<<2)) = *(const float4*)(kvw + (i<<2));

    auto issue = [&](int t, int s){
        if (t < NTILES){
            const int b = t >> 9; const size_t base = (size_t)(t & 511) << 7;
            const float* gy = yin + (size_t)b*64*HW + base;
            float* sY = buf + s*8192;
            #pragma unroll
            for (int i = tid; i < 2048; i += 256){
                const int c = i >> 5, off = (i & 31) << 2;
                cpa16(sY + c*128 + off, gy + (size_t)c*HW + off);
            }
        }
        cpa_commit();
    };

    int s = 0;
    issue(blockIdx.x, 0);
    for (int t = blockIdx.x; t < NTILES; t += gridDim.x){
        issue(t + gridDim.x, s ^ 1);
        cpa_wait1();
        __syncthreads();

        const float* sY = buf + s*8192;
        u64 av[16][2];
        #pragma unroll
        for (int i = 0; i < 16; ++i){ av[i][0]=av[i][1]=0ull; }

        #pragma unroll 4
        for (int k0 = 0; k0 < 64; k0 += 4){
            u64 yP[4][2];
            #pragma unroll
            for (int kk = 0; kk < 4; ++kk){
                float4 y4 = *(const float4*)(sY + (k0+kk)*128 + (tx<<2));
                yP[kk][0] = pk2(y4.x, y4.y); yP[kk][1] = pk2(y4.z, y4.w);
            }
            #pragma unroll
            for (int i = 0; i < 16; ++i){
                const int o = ty + (i<<3);
                float4 w = *(const float4*)(sW + o*64 + k0);
                fma_bcast(av[i], w.x, yP[0]); fma_bcast(av[i], w.y, yP[1]);
                fma_bcast(av[i], w.z, yP[2]); fma_bcast(av[i], w.w, yP[3]);
            }
        }
        const int b = t >> 9; const size_t base = (size_t)(t & 511) << 7;
        #pragma unroll
        for (int i = 0; i < 16; ++i){
            const int o = ty + (i<<3);
            float4 r; upk2(av[i][0], r.x, r.y); upk2(av[i][1], r.z, r.w);
            *(float4*)(g_kvm + ((size_t)(b*128 + o))*HW + base + (tx<<2)) = r;
        }
        __syncthreads();
        s ^= 1;
    }
}

// ---------------- K2a: depthwise 3x3, one channel-plane per block ----------------
// Block = 256 threads: 4 row-groups x 64 col-quads. Each thread: 4 rows x 4 cols.
// Loads 6 float4 rows; horizontal halo via warp shuffle (edge lanes load 1 scalar).
__global__ void __launch_bounds__(256) k2a_dw(
    const float* __restrict__ qdw, const float* __restrict__ kvdw)
{
    const int b = blockIdx.z, plane = blockIdx.y, band = blockIdx.x;
    const int kind = plane >> 6;           // 0=q, 1=k, 2=v
    const int c = plane & 63;

    const float* src; const float* w9;
    if (kind == 0){ src = g_qm  + ((size_t)(b*64  + c))*HW;      w9 = qdw  + c*9; }
    else if (kind == 1){ src = g_kvm + ((size_t)(b*128 + c))*HW; w9 = kvdw + c*9; }
    else { src = g_kvm + ((size_t)(b*128 + 64 + c))*HW;          w9 = kvdw + (64 + c)*9; }

    float w[9];
    #pragma unroll
    for (int i = 0; i < 9; ++i) w[i] = __ldg(w9 + i);

    const int tid = threadIdx.x;
    const int rg = tid >> 6, xq = tid & 63, xx = xq << 2;
    const int lane = tid & 31;
    const int y0 = band*16 + rg*4;

    float4 o[4];
    #pragma unroll
    for (int j = 0; j < 4; ++j) o[j] = make_float4(0.f, 0.f, 0.f, 0.f);

    #pragma unroll
    for (int i = 0; i < 6; ++i){
        const int ys = y0 - 1 + i;
        const bool yok = (ys >= 0) && (ys <= 255);
        const float* row = src + ys*256 + xx;
        float4 c4 = make_float4(0.f, 0.f, 0.f, 0.f);
        if (yok) c4 = __ldg((const float4*)row);
        float lv = __shfl_up_sync(0xffffffffu, c4.w, 1);
        float rv = __shfl_down_sync(0xffffffffu, c4.x, 1);
        if (lane == 0)  lv = (yok && xx > 0)   ? __ldg(row - 1) : 0.f;
        if (lane == 31) rv = (yok && xx < 252) ? __ldg(row + 4) : 0.f;

        #pragma unroll
        for (int j = 0; j < 4; ++j){
            const int ky = i - j;
            if (ky >= 0 && ky < 3){
                const float wa = w[ky*3], wb = w[ky*3+1], wc = w[ky*3+2];
                o[j].x += wa*lv   + wb*c4.x + wc*c4.y;
                o[j].y += wa*c4.x + wb*c4.y + wc*c4.z;
                o[j].z += wa*c4.y + wb*c4.z + wc*c4.w;
                o[j].w += wa*c4.z + wb*c4.w + wc*rv;
            }
        }
    }

    const size_t obase = ((size_t)(b*64 + c))*HW + (size_t)y0*256 + xx;

    if (kind == 2){
        #pragma unroll
        for (int j = 0; j < 4; ++j)
            *(float4*)(g_v + obase + j*256) = o[j];
        return;
    }

    // sum of squares (exact f32 values)
    float s = 0.f;
    #pragma unroll
    for (int j = 0; j < 4; ++j)
        s += o[j].x*o[j].x + o[j].y*o[j].y + o[j].z*o[j].z + o[j].w*o[j].w;
    #pragma unroll
    for (int off = 16; off; off >>= 1) s += __shfl_xor_sync(0xffffffffu, s, off);
    if (lane == 0)
        atomicAdd((kind == 0 ? g_qss : g_kss) + b*64 + c, s);

    unsigned* dst = (kind == 0 ? g_qb : g_kb);
    #pragma unroll
    for (int j = 0; j < 4; ++j){
        __nv_bfloat162 p0 = __floats2bfloat162_rn(o[j].x, o[j].y);
        __nv_bfloat162 p1 = __floats2bfloat162_rn(o[j].z, o[j].w);
        uint2 u;
        u.x = *(unsigned*)&p0;
        u.y = *(unsigned*)&p1;
        *(uint2*)(dst + ((obase + (size_t)j*256) >> 1)) = u;
    }
}

// ---------------- K2b: gram = q_dw @ k_dw^T over hw (bf16 in, f32 acc) ----------------
// grid (16 chunks, 4 heads, 8 batch). Block 256 thr: g=tid>>4 (16 subchunks of 256px),
// it,jt 4x4 tile of 4x4 channels. Thread: 32 iters x 8 px.
__device__ __forceinline__ float bflo(unsigned u){ return __int_as_float((int)(u << 16)); }
__device__ __forceinline__ float bfhi(unsigned u){ return __int_as_float((int)(u & 0xffff0000u)); }

__global__ void __launch_bounds__(256) k2b_gram()
{
    const int b = blockIdx.z, h = blockIdx.y, chunk = blockIdx.x;
    const int tid = threadIdx.x;
    const int g = tid >> 4, it = (tid >> 2) & 3, jt = tid & 3;
    const int p0 = chunk*4096 + g*256;

    const unsigned* qb = g_qb + (((size_t)(b*64 + h*16)) * HW >> 1);
    const unsigned* kb = g_kb + (((size_t)(b*64 + h*16)) * HW >> 1);

    float acc[4][4];
    #pragma unroll
    for (int a = 0; a < 4; ++a)
        #pragma unroll
        for (int d = 0; d < 4; ++d) acc[a][d] = 0.f;

    for (int p = p0; p < p0 + 256; p += 8){
        uint4 qu[4], ku[4];
        #pragma unroll
        for (int a = 0; a < 4; ++a){
            qu[a] = __ldg((const uint4*)(qb + (((size_t)(it*4 + a))*HW + p >> 1)));
            ku[a] = __ldg((const uint4*)(kb + (((size_t)(jt*4 + a))*HW + p >> 1)));
        }
        float qf[4][8], kf[4][8];
        #pragma unroll
        for (int a = 0; a < 4; ++a){
            qf[a][0]=bflo(qu[a].x); qf[a][1]=bfhi(qu[a].x);
            qf[a][2]=bflo(qu[a].y); qf[a][3]=bfhi(qu[a].y);
            qf[a][4]=bflo(qu[a].z); qf[a][5]=bfhi(qu[a].z);
            qf[a][6]=bflo(qu[a].w); qf[a][7]=bfhi(qu[a].w);
            kf[a][0]=bflo(ku[a].x); kf[a][1]=bfhi(ku[a].x);
            kf[a][2]=bflo(ku[a].y); kf[a][3]=bfhi(ku[a].y);
            kf[a][4]=bflo(ku[a].z); kf[a][5]=bfhi(ku[a].z);
            kf[a][6]=bflo(ku[a].w); kf[a][7]=bfhi(ku[a].w);
        }
        #pragma unroll
        for (int a = 0; a < 4; ++a)
            #pragma unroll
            for (int d = 0; d < 4; ++d){
                float t = 0.f;
                #pragma unroll
                for (int px = 0; px < 8; ++px) t += qf[a][px]*kf[d][px];
                acc[a][d] += t;
            }
    }
    #pragma unroll
    for (int a = 0; a < 4; ++a)
        #pragma unroll
        for (int d = 0; d < 4; ++d)
            atomicAdd(g_gram + (b*4 + h)*256 + (it*4 + a)*16 + (jt*4 + d), acc[a][d]);
}

// ---------------- K3: softmax + fold proj into per-batch 64x64 matrix M ----------------
__global__ void __launch_bounds__(256) k3_attn(
    const float* __restrict__ pjw, const float* __restrict__ temp)
{
    __shared__ float sA[1024];
    __shared__ float snq[64], snk[64];
    const int b = blockIdx.x, tid = threadIdx.x;
    if (tid < 64){
        snq[tid] = fmaxf(sqrtf(g_qss[b*64 + tid]), EPSN);
        snk[tid] = fmaxf(sqrtf(g_kss[b*64 + tid]), EPSN);
    }
    __syncthreads();
    if (tid < 64){
        const int h = tid >> 4;
        const float t = __ldg(temp + h);
        const float inq = t / snq[tid];
        const float* gr = g_gram + (b*4 + h)*256 + (tid & 15)*16;
        float l[16]; float mx = -1e30f;
        #pragma unroll
        for (int d = 0; d < 16; ++d){ l[d] = gr[d] * inq / snk[h*16 + d]; mx = fmaxf(mx, l[d]); }
        float ssum = 0.f;
        #pragma unroll
        for (int d = 0; d < 16; ++d){ l[d] = __expf(l[d] - mx); ssum += l[d]; }
        const float inv = 1.f / ssum;
        #pragma unroll
        for (int d = 0; d < 16; ++d) sA[tid*16 + d] = l[d] * inv;
    }
    __syncthreads();
    for (int idx = tid; idx < 4096; idx += 256){
        const int o = idx >> 6, cd = idx & 63, h = cd >> 4, d = cd & 15;
        float s = 0.f;
        #pragma unroll
        for (int ci = 0; ci < 16; ++ci)
            s += __ldg(pjw + o*64 + h*16 + ci) * sA[(h*16 + ci)*16 + d];
        g_M[b*4096 + idx] = s;
    }
}

// ---------------- K4: out = M[b] @ v, persistent + double-buffered ----------------
__global__ void __launch_bounds__(256, 2) k4_out(float* __restrict__ out)
{
    extern __shared__ float sm[];
    float* buf = sm;
    const int tid = threadIdx.x, tx = tid & 31, ty = tid >> 5;

    auto issue = [&](int t, int s){
        if (t < NTILES){
            const int b = t >> 9; const size_t base = (size_t)(t & 511) << 7;
            const float* gv = g_v + (size_t)b*64*HW + base;
            const float* gm = g_M + b*4096;
            float* sV = buf + s*12288; float* sM = sV + 8192;
            #pragma unroll
            for (int i = tid; i < 2048; i += 256){
                const int c = i >> 5, off = (i & 31) << 2;
                cpa16(sV + c*128 + off, gv + (size_t)c*HW + off);
            }
            #pragma unroll
            for (int i = tid; i < 1024; i += 256)
                cpa16(sM + (i<<2), gm + (i<<2));
        }
        cpa_commit();
    };

    int s = 0;
    issue(blockIdx.x, 0);
    for (int t = blockIdx.x; t < NTILES; t += gridDim.x){
        issue(t + gridDim.x, s ^ 1);
        cpa_wait1();
        __syncthreads();

        const float* sV = buf + s*12288; const float* sM = sV + 8192;
        u64 acc[8][2];
        #pragma unroll
        for (int i = 0; i < 8; ++i){ acc[i][0] = acc[i][1] = 0ull; }

        #pragma unroll 4
        for (int k0 = 0; k0 < 64; k0 += 4){
            u64 vP[4][2];
            #pragma unroll
            for (int kk = 0; kk < 4; ++kk){
                float4 v4 = *(const float4*)(sV + (k0+kk)*128 + (tx<<2));
                vP[kk][0] = pk2(v4.x, v4.y); vP[kk][1] = pk2(v4.z, v4.w);
            }
            #pragma unroll
            for (int i = 0; i < 8; ++i){
                float4 w = *(const float4*)(sM + (ty + (i<<3))*64 + k0);
                fma_bcast(acc[i], w.x, vP[0]); fma_bcast(acc[i], w.y, vP[1]);
                fma_bcast(acc[i], w.z, vP[2]); fma_bcast(acc[i], w.w, vP[3]);
            }
        }
        const int b = t >> 9; const size_t base = (size_t)(t & 511) << 7;
        #pragma unroll
        for (int i = 0; i < 8; ++i){
            const int o = ty + (i<<3);
            float4 r; upk2(acc[i][0], r.x, r.y); upk2(acc[i][1], r.z, r.w);
            *(float4*)(out + ((size_t)(b*64 + o))*HW + base + (tx<<2)) = r;
        }
        __syncthreads();
        s ^= 1;
    }
}

// ---------------- launch ----------------
extern "C" void kernel_launch(void* const* d_in, const int* in_sizes, int n_in,
                              void* d_out, int out_size)
{
    (void)in_sizes; (void)n_in; (void)out_size;
    const float* dg   = (const float*)d_in[0];
    const float* xin  = (const float*)d_in[1];
    const float* yin  = (const float*)d_in[2];
    const float* q1w  = (const float*)d_in[3];
    const float* q2w  = (const float*)d_in[4];
    const float* qdw  = (const float*)d_in[5];
    const float* kvw  = (const float*)d_in[6];
    const float* kvdw = (const float*)d_in[7];
    const float* pjw  = (const float*)d_in[8];
    const float* temp = (const float*)d_in[9];
    float* out = (float*)d_out;

    cudaFuncSetAttribute(k1a_q,  cudaFuncAttributeMaxDynamicSharedMemorySize, 163840);
    cudaFuncSetAttribute(k1b_kv, cudaFuncAttributeMaxDynamicSharedMemorySize, 98304);
    cudaFuncSetAttribute(k4_out, cudaFuncAttributeMaxDynamicSharedMemorySize, 98304);

    k0_init<<<32, 256>>>();
    k1a_q  <<<152, 256, 163840>>>(dg, xin, q1w, q2w);
    k1b_kv <<<304, 256,  98304>>>(yin, kvw);
    k2a_dw <<<dim3(16, 192, 8), 256>>>(qdw, kvdw);
    k2b_gram<<<dim3(16, 4, 8), 256>>>();
    k3_attn<<<8, 256>>>(pjw, temp);
    k4_out <<<304, 256,  98304>>>(out);
}

// round 4
// speedup vs baseline: 1.7651x; 1.0113x over previous
#include <cuda_runtime.h>
#include <cuda_bf16.h>
#include <cstdint>

#define HW 65536
#define EPSN 1e-12f

typedef unsigned long long u64;

// ---------------- scratch (static device globals; no allocation) ----------------
__device__ unsigned g_qmb[16777216]; // [8][64][32768] bf16-pair qm
__device__ unsigned g_kvl[16777216]; // [8][64][32768] bf16-pair kvm low (k source)
__device__ float    g_kvh[33554432]; // [8][64][65536] f32 kvm high (v source)
__device__ float    g_v  [33554432]; // [8][64][65536] v after dwconv
__device__ unsigned g_qb [16777216]; // [8][64][32768] bf16 q_dw
__device__ unsigned g_kb [16777216]; // [8][64][32768] bf16 k_dw
__device__ float g_gram[8192];       // [8][4][16][16]
__device__ float g_qss[512];         // [8][64]
__device__ float g_kss[512];         // [8][64]
__device__ float g_M  [32768];       // [8][64][64] fused proj*attn

// ---------------- f32x2 helpers ----------------
__device__ __forceinline__ u64 pk2(float lo, float hi){
    u64 r; asm("mov.b64 %0, {%1, %2};" : "=l"(r) : "f"(lo), "f"(hi)); return r;
}
__device__ __forceinline__ void upk2(u64 v, float& lo, float& hi){
    asm("mov.b64 {%0, %1}, %2;" : "=f"(lo), "=f"(hi) : "l"(v));
}
__device__ __forceinline__ u64 ffma2(u64 a, u64 b, u64 c){
    u64 d; asm("fma.rn.f32x2 %0, %1, %2, %3;" : "=l"(d) : "l"(a), "l"(b), "l"(c)); return d;
}
__device__ __forceinline__ u64 fmul2p(u64 a, u64 b){
    u64 d; asm("mul.rn.f32x2 %0, %1, %2;" : "=l"(d) : "l"(a), "l"(b)); return d;
}
__device__ __forceinline__ void fma_bcast(u64 (&acc)[2], float w, const u64 (&p)[2]){
    u64 wp = pk2(w, w);
    acc[0] = ffma2(wp, p[0], acc[0]);
    acc[1] = ffma2(wp, p[1], acc[1]);
}
__device__ __forceinline__ float bflo(unsigned u){ return __int_as_float((int)(u << 16)); }
__device__ __forceinline__ float bfhi(unsigned u){ return __int_as_float((int)(u & 0xffff0000u)); }
__device__ __forceinline__ unsigned pkbf(float a, float b){
    __nv_bfloat162 p = __floats2bfloat162_rn(a, b);
    return *(unsigned*)&p;
}

// ---------------- cp.async helpers ----------------
__device__ __forceinline__ void cpa16(void* smem, const void* g){
    unsigned s = (unsigned)__cvta_generic_to_shared(smem);
    asm volatile("cp.async.cg.shared.global [%0], [%1], 16;" :: "r"(s), "l"(g));
}
__device__ __forceinline__ void cpa_commit(){ asm volatile("cp.async.commit_group;"); }
__device__ __forceinline__ void cpa_wait1(){ asm volatile("cp.async.wait_group 1;"); }

// ---------------- K0: zero the accumulators (every replay) ----------------
__global__ void k0_init(){
    int i = blockIdx.x * 256 + threadIdx.x;
    if (i < 8192) g_gram[i] = 0.f;
    if (i < 512){ g_qss[i] = 0.f; g_kss[i] = 0.f; }
}

#define NTILES 4096   // 128-px tiles over 8 batches x 65536 px

// ---------------- K1a: q path (2 GEMMs), persistent + double-buffered, bf16 out ----------------
__global__ void __launch_bounds__(256, 1) k1a_q(
    const float* __restrict__ dg, const float* __restrict__ xin,
    const float* __restrict__ q1w, const float* __restrict__ q2w)
{
    extern __shared__ float sm[];
    float* sW1 = sm;
    float* sW2 = sm + 4096;
    float* buf = sm + 8192;
    const int tid = threadIdx.x, tx = tid & 31, ty = tid >> 5;

    for (int i = tid; i < 1024; i += 256){
        *(float4*)(sW1 + (i<<2)) = *(const float4*)(q1w + (i<<2));
        *(float4*)(sW2 + (i<<2)) = *(const float4*)(q2w + (i<<2));
    }

    auto issue = [&](int t, int s){
        if (t < NTILES){
            const int b = t >> 9; const size_t base = (size_t)(t & 511) << 7;
            const float* gd = dg  + (size_t)b*64*HW + base;
            const float* gx = xin + (size_t)b*64*HW + base;
            float* sD = buf + s*16384; float* sX = sD + 8192;
            #pragma unroll
            for (int i = tid; i < 2048; i += 256){
                const int c = i >> 5, off = (i & 31) << 2;
                cpa16(sD + c*128 + off, gd + (size_t)c*HW + off);
                cpa16(sX + c*128 + off, gx + (size_t)c*HW + off);
            }
        }
        cpa_commit();
    };

    int s = 0;
    issue(blockIdx.x, 0);
    for (int t = blockIdx.x; t < NTILES; t += gridDim.x){
        issue(t + gridDim.x, s ^ 1);
        cpa_wait1();
        __syncthreads();

        const float* sD = buf + s*16384; const float* sX = sD + 8192;
        u64 a1[8][2], a2[8][2];
        #pragma unroll
        for (int i = 0; i < 8; ++i){ a1[i][0]=a1[i][1]=a2[i][0]=a2[i][1]=0ull; }

        #pragma unroll 4
        for (int k0 = 0; k0 < 64; k0 += 4){
            u64 dP[4][2], xP[4][2];
            #pragma unroll
            for (int kk = 0; kk < 4; ++kk){
                float4 d4 = *(const float4*)(sD + (k0+kk)*128 + (tx<<2));
                dP[kk][0] = pk2(d4.x, d4.y); dP[kk][1] = pk2(d4.z, d4.w);
                float4 x4 = *(const float4*)(sX + (k0+kk)*128 + (tx<<2));
                xP[kk][0] = pk2(x4.x, x4.y); xP[kk][1] = pk2(x4.z, x4.w);
            }
            #pragma unroll
            for (int i = 0; i < 8; ++i){
                const int o = ty + (i<<3);
                float4 w1 = *(const float4*)(sW1 + o*64 + k0);
                float4 w2 = *(const float4*)(sW2 + o*64 + k0);
                fma_bcast(a1[i], w1.x, dP[0]); fma_bcast(a1[i], w1.y, dP[1]);
                fma_bcast(a1[i], w1.z, dP[2]); fma_bcast(a1[i], w1.w, dP[3]);
                fma_bcast(a2[i], w2.x, xP[0]); fma_bcast(a2[i], w2.y, xP[1]);
                fma_bcast(a2[i], w2.z, xP[2]); fma_bcast(a2[i], w2.w, xP[3]);
            }
        }
        const int b = t >> 9; const size_t base = (size_t)(t & 511) << 7;
        #pragma unroll
        for (int i = 0; i < 8; ++i){
            const int o = ty + (i<<3);
            u64 m0 = fmul2p(a1[i][0], a2[i][0]);
            u64 m1 = fmul2p(a1[i][1], a2[i][1]);
            float4 r; upk2(m0, r.x, r.y); upk2(m1, r.z, r.w);
            uint2 u; u.x = pkbf(r.x, r.y); u.y = pkbf(r.z, r.w);
            *(uint2*)(g_qmb + (((size_t)(b*64 + o))*HW + base + (tx<<2) >> 1)) = u;
        }
        __syncthreads();
        s ^= 1;
    }
}

// ---------------- K1b: kv GEMM (128 outs): k half -> bf16, v half -> f32 ----------------
__global__ void __launch_bounds__(256, 2) k1b_kv(
    const float* __restrict__ yin, const float* __restrict__ kvw)
{
    extern __shared__ float sm[];
    float* sW  = sm;
    float* buf = sm + 8192;
    const int tid = threadIdx.x, tx = tid & 31, ty = tid >> 5;

    for (int i = tid; i < 2048; i += 256)
        *(float4*)(sW + (i<<2)) = *(const float4*)(kvw + (i<<2));

    auto issue = [&](int t, int s){
        if (t < NTILES){
            const int b = t >> 9; const size_t base = (size_t)(t & 511) << 7;
            const float* gy = yin + (size_t)b*64*HW + base;
            float* sY = buf + s*8192;
            #pragma unroll
            for (int i = tid; i < 2048; i += 256){
                const int c = i >> 5, off = (i & 31) << 2;
                cpa16(sY + c*128 + off, gy + (size_t)c*HW + off);
            }
        }
        cpa_commit();
    };

    int s = 0;
    issue(blockIdx.x, 0);
    for (int t = blockIdx.x; t < NTILES; t += gridDim.x){
        issue(t + gridDim.x, s ^ 1);
        cpa_wait1();
        __syncthreads();

        const float* sY = buf + s*8192;
        u64 av[16][2];
        #pragma unroll
        for (int i = 0; i < 16; ++i){ av[i][0]=av[i][1]=0ull; }

        #pragma unroll 4
        for (int k0 = 0; k0 < 64; k0 += 4){
            u64 yP[4][2];
            #pragma unroll
            for (int kk = 0; kk < 4; ++kk){
                float4 y4 = *(const float4*)(sY + (k0+kk)*128 + (tx<<2));
                yP[kk][0] = pk2(y4.x, y4.y); yP[kk][1] = pk2(y4.z, y4.w);
            }
            #pragma unroll
            for (int i = 0; i < 16; ++i){
                const int o = ty + (i<<3);
                float4 w = *(const float4*)(sW + o*64 + k0);
                fma_bcast(av[i], w.x, yP[0]); fma_bcast(av[i], w.y, yP[1]);
                fma_bcast(av[i], w.z, yP[2]); fma_bcast(av[i], w.w, yP[3]);
            }
        }
        const int b = t >> 9; const size_t base = (size_t)(t & 511) << 7;
        #pragma unroll
        for (int i = 0; i < 8; ++i){     // k channels (o = ty+8i < 64) -> bf16
            const int o = ty + (i<<3);
            float4 r; upk2(av[i][0], r.x, r.y); upk2(av[i][1], r.z, r.w);
            uint2 u; u.x = pkbf(r.x, r.y); u.y = pkbf(r.z, r.w);
            *(uint2*)(g_kvl + (((size_t)(b*64 + o))*HW + base + (tx<<2) >> 1)) = u;
        }
        #pragma unroll
        for (int i = 8; i < 16; ++i){    // v channels -> f32
            const int o = ty + ((i - 8)<<3);
            float4 r; upk2(av[i][0], r.x, r.y); upk2(av[i][1], r.z, r.w);
            *(float4*)(g_kvh + ((size_t)(b*64 + o))*HW + base + (tx<<2)) = r;
        }
        __syncthreads();
        s ^= 1;
    }
}

// ---------------- K2a: depthwise 3x3, one channel-plane per block ----------------
__global__ void __launch_bounds__(256) k2a_dw(
    const float* __restrict__ qdw, const float* __restrict__ kvdw)
{
    const int b = blockIdx.z, plane = blockIdx.y, band = blockIdx.x;
    const int kind = plane >> 6;           // 0=q, 1=k, 2=v
    const int c = plane & 63;

    const float* w9;
    const unsigned* srcb = nullptr; const float* srcf = nullptr;
    if (kind == 0){ srcb = g_qmb + (((size_t)(b*64 + c))*HW >> 1); w9 = qdw  + c*9; }
    else if (kind == 1){ srcb = g_kvl + (((size_t)(b*64 + c))*HW >> 1); w9 = kvdw + c*9; }
    else { srcf = g_kvh + ((size_t)(b*64 + c))*HW; w9 = kvdw + (64 + c)*9; }

    float w[9];
    #pragma unroll
    for (int i = 0; i < 9; ++i) w[i] = __ldg(w9 + i);

    const int tid = threadIdx.x;
    const int rg = tid >> 6, xq = tid & 63, xx = xq << 2;
    const int lane = tid & 31;
    const int y0 = band*16 + rg*4;

    float4 o[4];
    #pragma unroll
    for (int j = 0; j < 4; ++j) o[j] = make_float4(0.f, 0.f, 0.f, 0.f);

    #pragma unroll
    for (int i = 0; i < 6; ++i){
        const int ys = y0 - 1 + i;
        const bool yok = (ys >= 0) && (ys <= 255);
        float4 c4 = make_float4(0.f, 0.f, 0.f, 0.f);
        float lv, rv;
        if (kind == 2){
            const float* row = srcf + ys*256 + xx;
            if (yok) c4 = __ldg((const float4*)row);
            lv = __shfl_up_sync(0xffffffffu, c4.w, 1);
            rv = __shfl_down_sync(0xffffffffu, c4.x, 1);
            if (lane == 0)  lv = (yok && xx > 0)   ? __ldg(row - 1) : 0.f;
            if (lane == 31) rv = (yok && xx < 252) ? __ldg(row + 4) : 0.f;
        } else {
            const unsigned* row = srcb + (ys << 7) + (xx >> 1);
            if (yok){
                uint2 u = __ldg((const uint2*)row);
                c4.x = bflo(u.x); c4.y = bfhi(u.x); c4.z = bflo(u.y); c4.w = bfhi(u.y);
            }
            lv = __shfl_up_sync(0xffffffffu, c4.w, 1);
            rv = __shfl_down_sync(0xffffffffu, c4.x, 1);
            if (lane == 0)  lv = (yok && xx > 0)   ? bfhi(__ldg(row - 1)) : 0.f;
            if (lane == 31) rv = (yok && xx < 252) ? bflo(__ldg(row + 2)) : 0.f;
        }

        #pragma unroll
        for (int j = 0; j < 4; ++j){
            const int ky = i - j;
            if (ky >= 0 && ky < 3){
                const float wa = w[ky*3], wb = w[ky*3+1], wc = w[ky*3+2];
                o[j].x += wa*lv   + wb*c4.x + wc*c4.y;
                o[j].y += wa*c4.x + wb*c4.y + wc*c4.z;
                o[j].z += wa*c4.y + wb*c4.z + wc*c4.w;
                o[j].w += wa*c4.z + wb*c4.w + wc*rv;
            }
        }
    }

    const size_t obase = ((size_t)(b*64 + c))*HW + (size_t)y0*256 + xx;

    if (kind == 2){
        #pragma unroll
        for (int j = 0; j < 4; ++j)
            *(float4*)(g_v + obase + j*256) = o[j];
        return;
    }

    float s = 0.f;
    #pragma unroll
    for (int j = 0; j < 4; ++j)
        s += o[j].x*o[j].x + o[j].y*o[j].y + o[j].z*o[j].z + o[j].w*o[j].w;
    #pragma unroll
    for (int off = 16; off; off >>= 1) s += __shfl_xor_sync(0xffffffffu, s, off);
    if (lane == 0)
        atomicAdd((kind == 0 ? g_qss : g_kss) + b*64 + c, s);

    unsigned* dst = (kind == 0 ? g_qb : g_kb);
    #pragma unroll
    for (int j = 0; j < 4; ++j){
        uint2 u;
        u.x = pkbf(o[j].x, o[j].y);
        u.y = pkbf(o[j].z, o[j].w);
        *(uint2*)(dst + ((obase + (size_t)j*256) >> 1)) = u;
    }
}

// ---------------- K2b: gram = q_dw @ k_dw^T (bf16 in, f32 acc) ----------------
__global__ void __launch_bounds__(256) k2b_gram()
{
    const int b = blockIdx.z, h = blockIdx.y, chunk = blockIdx.x;
    const int tid = threadIdx.x;
    const int g = tid >> 4, it = (tid >> 2) & 3, jt = tid & 3;
    const int p0 = chunk*4096 + g*256;

    const unsigned* qb = g_qb + (((size_t)(b*64 + h*16)) * HW >> 1);
    const unsigned* kb = g_kb + (((size_t)(b*64 + h*16)) * HW >> 1);

    float acc[4][4];
    #pragma unroll
    for (int a = 0; a < 4; ++a)
        #pragma unroll
        for (int d = 0; d < 4; ++d) acc[a][d] = 0.f;

    for (int p = p0; p < p0 + 256; p += 8){
        uint4 qu[4], ku[4];
        #pragma unroll
        for (int a = 0; a < 4; ++a){
            qu[a] = __ldg((const uint4*)(qb + (((size_t)(it*4 + a))*HW + p >> 1)));
            ku[a] = __ldg((const uint4*)(kb + (((size_t)(jt*4 + a))*HW + p >> 1)));
        }
        float qf[4][8], kf[4][8];
        #pragma unroll
        for (int a = 0; a < 4; ++a){
            qf[a][0]=bflo(qu[a].x); qf[a][1]=bfhi(qu[a].x);
            qf[a][2]=bflo(qu[a].y); qf[a][3]=bfhi(qu[a].y);
            qf[a][4]=bflo(qu[a].z); qf[a][5]=bfhi(qu[a].z);
            qf[a][6]=bflo(qu[a].w); qf[a][7]=bfhi(qu[a].w);
            kf[a][0]=bflo(ku[a].x); kf[a][1]=bfhi(ku[a].x);
            kf[a][2]=bflo(ku[a].y); kf[a][3]=bfhi(ku[a].y);
            kf[a][4]=bflo(ku[a].z); kf[a][5]=bfhi(ku[a].z);
            kf[a][6]=bflo(ku[a].w); kf[a][7]=bfhi(ku[a].w);
        }
        #pragma unroll
        for (int a = 0; a < 4; ++a)
            #pragma unroll
            for (int d = 0; d < 4; ++d){
                float t = 0.f;
                #pragma unroll
                for (int px = 0; px < 8; ++px) t += qf[a][px]*kf[d][px];
                acc[a][d] += t;
            }
    }
    #pragma unroll
    for (int a = 0; a < 4; ++a)
        #pragma unroll
        for (int d = 0; d < 4; ++d)
            atomicAdd(g_gram + (b*4 + h)*256 + (it*4 + a)*16 + (jt*4 + d), acc[a][d]);
}

// ---------------- K3: softmax + fold proj into per-batch 64x64 matrix M ----------------
__global__ void __launch_bounds__(256) k3_attn(
    const float* __restrict__ pjw, const float* __restrict__ temp)
{
    __shared__ float sA[1024];
    __shared__ float snq[64], snk[64];
    const int b = blockIdx.x, tid = threadIdx.x;
    if (tid < 64){
        snq[tid] = fmaxf(sqrtf(g_qss[b*64 + tid]), EPSN);
        snk[tid] = fmaxf(sqrtf(g_kss[b*64 + tid]), EPSN);
    }
    __syncthreads();
    if (tid < 64){
        const int h = tid >> 4;
        const float t = __ldg(temp + h);
        const float inq = t / snq[tid];
        const float* gr = g_gram + (b*4 + h)*256 + (tid & 15)*16;
        float l[16]; float mx = -1e30f;
        #pragma unroll
        for (int d = 0; d < 16; ++d){ l[d] = gr[d] * inq / snk[h*16 + d]; mx = fmaxf(mx, l[d]); }
        float ssum = 0.f;
        #pragma unroll
        for (int d = 0; d < 16; ++d){ l[d] = __expf(l[d] - mx); ssum += l[d]; }
        const float inv = 1.f / ssum;
        #pragma unroll
        for (int d = 0; d < 16; ++d) sA[tid*16 + d] = l[d] * inv;
    }
    __syncthreads();
    for (int idx = tid; idx < 4096; idx += 256){
        const int o = idx >> 6, cd = idx & 63, h = cd >> 4, d = cd & 15;
        float s = 0.f;
        #pragma unroll
        for (int ci = 0; ci < 16; ++ci)
            s += __ldg(pjw + o*64 + h*16 + ci) * sA[(h*16 + ci)*16 + d];
        g_M[b*4096 + idx] = s;
    }
}

// ---------------- K4: out = M[b] @ v, persistent + double-buffered ----------------
__global__ void __launch_bounds__(256, 2) k4_out(float* __restrict__ out)
{
    extern __shared__ float sm[];
    float* buf = sm;
    const int tid = threadIdx.x, tx = tid & 31, ty = tid >> 5;

    auto issue = [&](int t, int s){
        if (t < NTILES){
            const int b = t >> 9; const size_t base = (size_t)(t & 511) << 7;
            const float* gv = g_v + (size_t)b*64*HW + base;
            const float* gm = g_M + b*4096;
            float* sV = buf + s*12288; float* sM = sV + 8192;
            #pragma unroll
            for (int i = tid; i < 2048; i += 256){
                const int c = i >> 5, off = (i & 31) << 2;
                cpa16(sV + c*128 + off, gv + (size_t)c*HW + off);
            }
            #pragma unroll
            for (int i = tid; i < 1024; i += 256)
                cpa16(sM + (i<<2), gm + (i<<2));
        }
        cpa_commit();
    };

    int s = 0;
    issue(blockIdx.x, 0);
    for (int t = blockIdx.x; t < NTILES; t += gridDim.x){
        issue(t + gridDim.x, s ^ 1);
        cpa_wait1();
        __syncthreads();

        const float* sV = buf + s*12288; const float* sM = sV + 8192;
        u64 acc[8][2];
        #pragma unroll
        for (int i = 0; i < 8; ++i){ acc[i][0] = acc[i][1] = 0ull; }

        #pragma unroll 4
        for (int k0 = 0; k0 < 64; k0 += 4){
            u64 vP[4][2];
            #pragma unroll
            for (int kk = 0; kk < 4; ++kk){
                float4 v4 = *(const float4*)(sV + (k0+kk)*128 + (tx<<2));
                vP[kk][0] = pk2(v4.x, v4.y); vP[kk][1] = pk2(v4.z, v4.w);
            }
            #pragma unroll
            for (int i = 0; i < 8; ++i){
                float4 w = *(const float4*)(sM + (ty + (i<<3))*64 + k0);
                fma_bcast(acc[i], w.x, vP[0]); fma_bcast(acc[i], w.y, vP[1]);
                fma_bcast(acc[i], w.z, vP[2]); fma_bcast(acc[i], w.w, vP[3]);
            }
        }
        const int b = t >> 9; const size_t base = (size_t)(t & 511) << 7;
        #pragma unroll
        for (int i = 0; i < 8; ++i){
            const int o = ty + (i<<3);
            float4 r; upk2(acc[i][0], r.x, r.y); upk2(acc[i][1], r.z, r.w);
            *(float4*)(out + ((size_t)(b*64 + o))*HW + base + (tx<<2)) = r;
        }
        __syncthreads();
        s ^= 1;
    }
}

// ---------------- launch ----------------
extern "C" void kernel_launch(void* const* d_in, const int* in_sizes, int n_in,
                              void* d_out, int out_size)
{
    (void)in_sizes; (void)n_in; (void)out_size;
    const float* dg   = (const float*)d_in[0];
    const float* xin  = (const float*)d_in[1];
    const float* yin  = (const float*)d_in[2];
    const float* q1w  = (const float*)d_in[3];
    const float* q2w  = (const float*)d_in[4];
    const float* qdw  = (const float*)d_in[5];
    const float* kvw  = (const float*)d_in[6];
    const float* kvdw = (const float*)d_in[7];
    const float* pjw  = (const float*)d_in[8];
    const float* temp = (const float*)d_in[9];
    float* out = (float*)d_out;

    cudaFuncSetAttribute(k1a_q,  cudaFuncAttributeMaxDynamicSharedMemorySize, 163840);
    cudaFuncSetAttribute(k1b_kv, cudaFuncAttributeMaxDynamicSharedMemorySize, 98304);
    cudaFuncSetAttribute(k4_out, cudaFuncAttributeMaxDynamicSharedMemorySize, 98304);

    k0_init<<<32, 256>>>();
    k1a_q  <<<152, 256, 163840>>>(dg, xin, q1w, q2w);
    k1b_kv <<<304, 256,  98304>>>(yin, kvw);
    k2a_dw <<<dim3(16, 192, 8), 256>>>(qdw, kvdw);
    k2b_gram<<<dim3(16, 4, 8), 256>>>();
    k3_attn<<<8, 256>>>(pjw, temp);
    k4_out <<<304, 256,  98304>>>(out);
}

// round 6
// speedup vs baseline: 1.9203x; 1.0879x over previous
#include <cuda_runtime.h>
#include <cuda_bf16.h>
#include <cstdint>

#define HW 65536
#define EPSN 1e-12f

typedef unsigned long long u64;

// ---------------- scratch (static device globals; no allocation) ----------------
__device__ unsigned g_qmb[16777216]; // [8][64][32768] bf16-pair qm
__device__ unsigned g_kvl[16777216]; // [8][64][32768] bf16-pair kvm low (k source)
__device__ float    g_kvh[33554432]; // [8][64][65536] f32 kvm high (v source)
__device__ float    g_v  [33554432]; // [8][64][65536] v after dwconv
__device__ unsigned g_qb [16777216]; // [8][64][32768] bf16 q_dw
__device__ unsigned g_kb [16777216]; // [8][64][32768] bf16 k_dw
__device__ float g_gram[8192];       // [8][4][16][16]
__device__ float g_qss[512];         // [8][64]
__device__ float g_kss[512];         // [8][64]
__device__ float g_M  [32768];       // [8][64][64] fused proj*attn

// ---------------- f32x2 helpers ----------------
__device__ __forceinline__ u64 pk2(float lo, float hi){
    u64 r; asm("mov.b64 %0, {%1, %2};" : "=l"(r) : "f"(lo), "f"(hi)); return r;
}
__device__ __forceinline__ void upk2(u64 v, float& lo, float& hi){
    asm("mov.b64 {%0, %1}, %2;" : "=f"(lo), "=f"(hi) : "l"(v));
}
__device__ __forceinline__ u64 ffma2(u64 a, u64 b, u64 c){
    u64 d; asm("fma.rn.f32x2 %0, %1, %2, %3;" : "=l"(d) : "l"(a), "l"(b), "l"(c)); return d;
}
__device__ __forceinline__ void fma_bcast(u64 (&acc)[2], float w, const u64 (&p)[2]){
    u64 wp = pk2(w, w);
    acc[0] = ffma2(wp, p[0], acc[0]);
    acc[1] = ffma2(wp, p[1], acc[1]);
}
__device__ __forceinline__ float bflo(unsigned u){ return __int_as_float((int)(u << 16)); }
__device__ __forceinline__ float bfhi(unsigned u){ return __int_as_float((int)(u & 0xffff0000u)); }
__device__ __forceinline__ unsigned pkbf(float a, float b){
    __nv_bfloat162 p = __floats2bfloat162_rn(a, b);
    return *(unsigned*)&p;
}

// ---------------- cp.async helpers ----------------
__device__ __forceinline__ void cpa16(void* smem, const void* g){
    unsigned s = (unsigned)__cvta_generic_to_shared(smem);
    asm volatile("cp.async.cg.shared.global [%0], [%1], 16;" :: "r"(s), "l"(g));
}
__device__ __forceinline__ void cpa_commit(){ asm volatile("cp.async.commit_group;"); }
__device__ __forceinline__ void cpa_wait1(){ asm volatile("cp.async.wait_group 1;"); }

// ---------------- warp mma (arch-generic bf16 HMMA) ----------------
__device__ __forceinline__ void mma16816(float* c, const unsigned* a, const unsigned* b){
    asm volatile("mma.sync.aligned.m16n8k16.row.col.f32.bf16.bf16.f32 "
        "{%0,%1,%2,%3}, {%4,%5,%6,%7}, {%8,%9}, {%0,%1,%2,%3};"
        : "+f"(c[0]), "+f"(c[1]), "+f"(c[2]), "+f"(c[3])
        : "r"(a[0]), "r"(a[1]), "r"(a[2]), "r"(a[3]), "r"(b[0]), "r"(b[1]));
}

// ---------------- K0: zero the accumulators (every replay) ----------------
__global__ void k0_init(){
    int i = blockIdx.x * 256 + threadIdx.x;
    if (i < 8192) g_gram[i] = 0.f;
    if (i < 512){ g_qss[i] = 0.f; g_kss[i] = 0.f; }
}

#define NTILES 4096   // 128-px tiles over 8 batches x 65536 px
#define ROWW 36       // smem row stride in 32-bit words (72 bf16, padded)

// ---------------- K1a: q path via mma.sync bf16 ----------------
// smem: sD,sX = [128 px][36 words] each (36864 B total)
__global__ void __launch_bounds__(256, 3) k1a_mma(
    const float* __restrict__ dg, const float* __restrict__ xin,
    const float* __restrict__ q1w, const float* __restrict__ q2w)
{
    extern __shared__ unsigned smk[];
    unsigned* sD = smk;
    unsigned* sX = smk + 128*ROWW;
    const int tid = threadIdx.x, wid = tid >> 5, lane = tid & 31;
    const int mb = wid & 3, nh = wid >> 2;
    const int grow = lane >> 2, t = lane & 3;

    // preload A fragments (weights) once: W1, W2, 4 k-chunks each
    unsigned aW1[4][4], aW2[4][4];
    {
        const int r0 = mb*16 + grow;
        #pragma unroll
        for (int cc = 0; cc < 4; ++cc){
            const int k0 = cc*16 + t*2;
            aW1[cc][0] = pkbf(__ldg(q1w + r0*64 + k0),       __ldg(q1w + r0*64 + k0 + 1));
            aW1[cc][1] = pkbf(__ldg(q1w + (r0+8)*64 + k0),   __ldg(q1w + (r0+8)*64 + k0 + 1));
            aW1[cc][2] = pkbf(__ldg(q1w + r0*64 + k0 + 8),   __ldg(q1w + r0*64 + k0 + 9));
            aW1[cc][3] = pkbf(__ldg(q1w + (r0+8)*64 + k0+8), __ldg(q1w + (r0+8)*64 + k0 + 9));
            aW2[cc][0] = pkbf(__ldg(q2w + r0*64 + k0),       __ldg(q2w + r0*64 + k0 + 1));
            aW2[cc][1] = pkbf(__ldg(q2w + (r0+8)*64 + k0),   __ldg(q2w + (r0+8)*64 + k0 + 1));
            aW2[cc][2] = pkbf(__ldg(q2w + r0*64 + k0 + 8),   __ldg(q2w + r0*64 + k0 + 9));
            aW2[cc][3] = pkbf(__ldg(q2w + (r0+8)*64 + k0+8), __ldg(q2w + (r0+8)*64 + k0 + 9));
        }
    }

    auto cvt = [&](const float* gsrc, unsigned* sT){
        #pragma unroll
        for (int j = 0; j < 8; ++j){
            const int idx = tid + j*256;
            const int ch = idx & 63;
            const int px0 = (idx >> 6) << 2;
            float4 v = __ldg((const float4*)(gsrc + (size_t)ch*HW + px0));
            float o0 = __shfl_xor_sync(0xffffffffu, v.x, 1);
            float o1 = __shfl_xor_sync(0xffffffffu, v.y, 1);
            float o2 = __shfl_xor_sync(0xffffffffu, v.z, 1);
            float o3 = __shfl_xor_sync(0xffffffffu, v.w, 1);
            const int cp = ch >> 1;
            if (!(ch & 1)){
                sT[(px0    )*ROWW + cp] = pkbf(v.x, o0);
                sT[(px0 + 1)*ROWW + cp] = pkbf(v.y, o1);
            } else {
                sT[(px0 + 2)*ROWW + cp] = pkbf(o2, v.z);
                sT[(px0 + 3)*ROWW + cp] = pkbf(o3, v.w);
            }
        }
    };

    for (int tt = blockIdx.x; tt < NTILES; tt += gridDim.x){
        const int bb = tt >> 9;
        const size_t pxb = (size_t)(tt & 511) << 7;

        cvt(dg  + (size_t)bb*64*HW + pxb, sD);
        cvt(xin + (size_t)bb*64*HW + pxb, sX);
        __syncthreads();

        const int pxw0 = (int)(pxb >> 1);
        #pragma unroll
        for (int nt = 0; nt < 8; ++nt){
            const int nb = nh*64 + nt*8;
            const int nrow = nb + grow;
            float ac1[4] = {0.f, 0.f, 0.f, 0.f};
            float ac2[4] = {0.f, 0.f, 0.f, 0.f};
            #pragma unroll
            for (int cc = 0; cc < 4; ++cc){
                unsigned bD[2], bX[2];
                const int w0 = nrow*ROWW + cc*8 + t;
                bD[0] = sD[w0]; bD[1] = sD[w0 + 4];
                bX[0] = sX[w0]; bX[1] = sX[w0 + 4];
                mma16816(ac1, aW1[cc], bD);
                mma16816(ac2, aW2[cc], bX);
            }
            const int ch = bb*64 + mb*16 + grow;
            const int pxp = pxw0 + (nb >> 1) + t;
            g_qmb[(size_t)ch*32768 + pxp]       = pkbf(ac1[0]*ac2[0], ac1[1]*ac2[1]);
            g_qmb[(size_t)(ch + 8)*32768 + pxp] = pkbf(ac1[2]*ac2[2], ac1[3]*ac2[3]);
        }
        __syncthreads();
    }
}

// ---------------- K1b: kv GEMM (128 outs): k half -> bf16, v half -> f32 ----------------
__global__ void __launch_bounds__(256, 2) k1b_kv(
    const float* __restrict__ yin, const float* __restrict__ kvw)
{
    extern __shared__ float sm[];
    float* sW  = sm;
    float* buf = sm + 8192;
    const int tid = threadIdx.x, tx = tid & 31, ty = tid >> 5;

    for (int i = tid; i < 2048; i += 256)
        *(float4*)(sW + (i<<2)) = *(const float4*)(kvw + (i<<2));

    auto issue = [&](int t, int s){
        if (t < NTILES){
            const int b = t >> 9; const size_t base = (size_t)(t & 511) << 7;
            const float* gy = yin + (size_t)b*64*HW + base;
            float* sY = buf + s*8192;
            #pragma unroll
            for (int i = tid; i < 2048; i += 256){
                const int c = i >> 5, off = (i & 31) << 2;
                cpa16(sY + c*128 + off, gy + (size_t)c*HW + off);
            }
        }
        cpa_commit();
    };

    int s = 0;
    issue(blockIdx.x, 0);
    for (int t = blockIdx.x; t < NTILES; t += gridDim.x){
        issue(t + gridDim.x, s ^ 1);
        cpa_wait1();
        __syncthreads();

        const float* sY = buf + s*8192;
        u64 av[16][2];
        #pragma unroll
        for (int i = 0; i < 16; ++i){ av[i][0]=av[i][1]=0ull; }

        #pragma unroll 4
        for (int k0 = 0; k0 < 64; k0 += 4){
            u64 yP[4][2];
            #pragma unroll
            for (int kk = 0; kk < 4; ++kk){
                float4 y4 = *(const float4*)(sY + (k0+kk)*128 + (tx<<2));
                yP[kk][0] = pk2(y4.x, y4.y); yP[kk][1] = pk2(y4.z, y4.w);
            }
            #pragma unroll
            for (int i = 0; i < 16; ++i){
                const int o = ty + (i<<3);
                float4 w = *(const float4*)(sW + o*64 + k0);
                fma_bcast(av[i], w.x, yP[0]); fma_bcast(av[i], w.y, yP[1]);
                fma_bcast(av[i], w.z, yP[2]); fma_bcast(av[i], w.w, yP[3]);
            }
        }
        const int b = t >> 9; const size_t base = (size_t)(t & 511) << 7;
        #pragma unroll
        for (int i = 0; i < 8; ++i){     // k channels -> bf16
            const int o = ty + (i<<3);
            float4 r; upk2(av[i][0], r.x, r.y); upk2(av[i][1], r.z, r.w);
            uint2 u; u.x = pkbf(r.x, r.y); u.y = pkbf(r.z, r.w);
            *(uint2*)(g_kvl + (((size_t)(b*64 + o))*HW + base + (tx<<2) >> 1)) = u;
        }
        #pragma unroll
        for (int i = 8; i < 16; ++i){    // v channels -> f32
            const int o = ty + ((i - 8)<<3);
            float4 r; upk2(av[i][0], r.x, r.y); upk2(av[i][1], r.z, r.w);
            *(float4*)(g_kvh + ((size_t)(b*64 + o))*HW + base + (tx<<2)) = r;
        }
        __syncthreads();
        s ^= 1;
    }
}

// ---------------- K2a: depthwise 3x3, one channel-plane per block ----------------
__global__ void __launch_bounds__(256) k2a_dw(
    const float* __restrict__ qdw, const float* __restrict__ kvdw)
{
    const int b = blockIdx.z, plane = blockIdx.y, band = blockIdx.x;
    const int kind = plane >> 6;           // 0=q, 1=k, 2=v
    const int c = plane & 63;

    const float* w9;
    const unsigned* srcb = nullptr; const float* srcf = nullptr;
    if (kind == 0){ srcb = g_qmb + (((size_t)(b*64 + c))*HW >> 1); w9 = qdw  + c*9; }
    else if (kind == 1){ srcb = g_kvl + (((size_t)(b*64 + c))*HW >> 1); w9 = kvdw + c*9; }
    else { srcf = g_kvh + ((size_t)(b*64 + c))*HW; w9 = kvdw + (64 + c)*9; }

    float w[9];
    #pragma unroll
    for (int i = 0; i < 9; ++i) w[i] = __ldg(w9 + i);

    const int tid = threadIdx.x;
    const int rg = tid >> 6, xq = tid & 63, xx = xq << 2;
    const int lane = tid & 31;
    const int y0 = band*16 + rg*4;

    float4 o[4];
    #pragma unroll
    for (int j = 0; j < 4; ++j) o[j] = make_float4(0.f, 0.f, 0.f, 0.f);

    #pragma unroll
    for (int i = 0; i < 6; ++i){
        const int ys = y0 - 1 + i;
        const bool yok = (ys >= 0) && (ys <= 255);
        float4 c4 = make_float4(0.f, 0.f, 0.f, 0.f);
        float lv, rv;
        if (kind == 2){
            const float* row = srcf + ys*256 + xx;
            if (yok) c4 = __ldg((const float4*)row);
            lv = __shfl_up_sync(0xffffffffu, c4.w, 1);
            rv = __shfl_down_sync(0xffffffffu, c4.x, 1);
            if (lane == 0)  lv = (yok && xx > 0)   ? __ldg(row - 1) : 0.f;
            if (lane == 31) rv = (yok && xx < 252) ? __ldg(row + 4) : 0.f;
        } else {
            const unsigned* row = srcb + (ys << 7) + (xx >> 1);
            if (yok){
                uint2 u = __ldg((const uint2*)row);
                c4.x = bflo(u.x); c4.y = bfhi(u.x); c4.z = bflo(u.y); c4.w = bfhi(u.y);
            }
            lv = __shfl_up_sync(0xffffffffu, c4.w, 1);
            rv = __shfl_down_sync(0xffffffffu, c4.x, 1);
            if (lane == 0)  lv = (yok && xx > 0)   ? bfhi(__ldg(row - 1)) : 0.f;
            if (lane == 31) rv = (yok && xx < 252) ? bflo(__ldg(row + 2)) : 0.f;
        }

        #pragma unroll
        for (int j = 0; j < 4; ++j){
            const int ky = i - j;
            if (ky >= 0 && ky < 3){
                const float wa = w[ky*3], wb = w[ky*3+1], wc = w[ky*3+2];
                o[j].x += wa*lv   + wb*c4.x + wc*c4.y;
                o[j].y += wa*c4.x + wb*c4.y + wc*c4.z;
                o[j].z += wa*c4.y + wb*c4.z + wc*c4.w;
                o[j].w += wa*c4.z + wb*c4.w + wc*rv;
            }
        }
    }

    const size_t obase = ((size_t)(b*64 + c))*HW + (size_t)y0*256 + xx;

    if (kind == 2){
        #pragma unroll
        for (int j = 0; j < 4; ++j)
            *(float4*)(g_v + obase + j*256) = o[j];
        return;
    }

    float s = 0.f;
    #pragma unroll
    for (int j = 0; j < 4; ++j)
        s += o[j].x*o[j].x + o[j].y*o[j].y + o[j].z*o[j].z + o[j].w*o[j].w;
    #pragma unroll
    for (int off = 16; off; off >>= 1) s += __shfl_xor_sync(0xffffffffu, s, off);
    if (lane == 0)
        atomicAdd((kind == 0 ? g_qss : g_kss) + b*64 + c, s);

    unsigned* dst = (kind == 0 ? g_qb : g_kb);
    #pragma unroll
    for (int j = 0; j < 4; ++j){
        uint2 u;
        u.x = pkbf(o[j].x, o[j].y);
        u.y = pkbf(o[j].z, o[j].w);
        *(uint2*)(dst + ((obase + (size_t)j*256) >> 1)) = u;
    }
}

// ---------------- K2b: gram = q_dw @ k_dw^T (bf16 in, f32 acc) ----------------
__global__ void __launch_bounds__(256) k2b_gram()
{
    const int b = blockIdx.z, h = blockIdx.y, chunk = blockIdx.x;
    const int tid = threadIdx.x;
    const int g = tid >> 4, it = (tid >> 2) & 3, jt = tid & 3;
    const int p0 = chunk*4096 + g*256;

    const unsigned* qb = g_qb + (((size_t)(b*64 + h*16)) * HW >> 1);
    const unsigned* kb = g_kb + (((size_t)(b*64 + h*16)) * HW >> 1);

    float acc[4][4];
    #pragma unroll
    for (int a = 0; a < 4; ++a)
        #pragma unroll
        for (int d = 0; d < 4; ++d) acc[a][d] = 0.f;

    for (int p = p0; p < p0 + 256; p += 8){
        uint4 qu[4], ku[4];
        #pragma unroll
        for (int a = 0; a < 4; ++a){
            qu[a] = __ldg((const uint4*)(qb + (((size_t)(it*4 + a))*HW + p >> 1)));
            ku[a] = __ldg((const uint4*)(kb + (((size_t)(jt*4 + a))*HW + p >> 1)));
        }
        float qf[4][8], kf[4][8];
        #pragma unroll
        for (int a = 0; a < 4; ++a){
            qf[a][0]=bflo(qu[a].x); qf[a][1]=bfhi(qu[a].x);
            qf[a][2]=bflo(qu[a].y); qf[a][3]=bfhi(qu[a].y);
            qf[a][4]=bflo(qu[a].z); qf[a][5]=bfhi(qu[a].z);
            qf[a][6]=bflo(qu[a].w); qf[a][7]=bfhi(qu[a].w);
            kf[a][0]=bflo(ku[a].x); kf[a][1]=bfhi(ku[a].x);
            kf[a][2]=bflo(ku[a].y); kf[a][3]=bfhi(ku[a].y);
            kf[a][4]=bflo(ku[a].z); kf[a][5]=bfhi(ku[a].z);
            kf[a][6]=bflo(ku[a].w); kf[a][7]=bfhi(ku[a].w);
        }
        #pragma unroll
        for (int a = 0; a < 4; ++a)
            #pragma unroll
            for (int d = 0; d < 4; ++d){
                float t = 0.f;
                #pragma unroll
                for (int px = 0; px < 8; ++px) t += qf[a][px]*kf[d][px];
                acc[a][d] += t;
            }
    }
    #pragma unroll
    for (int a = 0; a < 4; ++a)
        #pragma unroll
        for (int d = 0; d < 4; ++d)
            atomicAdd(g_gram + (b*4 + h)*256 + (it*4 + a)*16 + (jt*4 + d), acc[a][d]);
}

// ---------------- K3: softmax + fold proj into per-batch 64x64 matrix M ----------------
__global__ void __launch_bounds__(256) k3_attn(
    const float* __restrict__ pjw, const float* __restrict__ temp)
{
    __shared__ float sA[1024];
    __shared__ float snq[64], snk[64];
    const int b = blockIdx.x, tid = threadIdx.x;
    if (tid < 64){
        snq[tid] = fmaxf(sqrtf(g_qss[b*64 + tid]), EPSN);
        snk[tid] = fmaxf(sqrtf(g_kss[b*64 + tid]), EPSN);
    }
    __syncthreads();
    if (tid < 64){
        const int h = tid >> 4;
        const float t = __ldg(temp + h);
        const float inq = t / snq[tid];
        const float* gr = g_gram + (b*4 + h)*256 + (tid & 15)*16;
        float l[16]; float mx = -1e30f;
        #pragma unroll
        for (int d = 0; d < 16; ++d){ l[d] = gr[d] * inq / snk[h*16 + d]; mx = fmaxf(mx, l[d]); }
        float ssum = 0.f;
        #pragma unroll
        for (int d = 0; d < 16; ++d){ l[d] = __expf(l[d] - mx); ssum += l[d]; }
        const float inv = 1.f / ssum;
        #pragma unroll
        for (int d = 0; d < 16; ++d) sA[tid*16 + d] = l[d] * inv;
    }
    __syncthreads();
    for (int idx = tid; idx < 4096; idx += 256){
        const int o = idx >> 6, cd = idx & 63, h = cd >> 4, d = cd & 15;
        float s = 0.f;
        #pragma unroll
        for (int ci = 0; ci < 16; ++ci)
            s += __ldg(pjw + o*64 + h*16 + ci) * sA[(h*16 + ci)*16 + d];
        g_M[b*4096 + idx] = s;
    }
}

// ---------------- K4: out = M[b] @ v, persistent + double-buffered ----------------
__global__ void __launch_bounds__(256, 2) k4_out(float* __restrict__ out)
{
    extern __shared__ float sm[];
    float* buf = sm;
    const int tid = threadIdx.x, tx = tid & 31, ty = tid >> 5;

    auto issue = [&](int t, int s){
        if (t < NTILES){
            const int b = t >> 9; const size_t base = (size_t)(t & 511) << 7;
            const float* gv = g_v + (size_t)b*64*HW + base;
            const float* gm = g_M + b*4096;
            float* sV = buf + s*12288; float* sM = sV + 8192;
            #pragma unroll
            for (int i = tid; i < 2048; i += 256){
                const int c = i >> 5, off = (i & 31) << 2;
                cpa16(sV + c*128 + off, gv + (size_t)c*HW + off);
            }
            #pragma unroll
            for (int i = tid; i < 1024; i += 256)
                cpa16(sM + (i<<2), gm + (i<<2));
        }
        cpa_commit();
    };

    int s = 0;
    issue(blockIdx.x, 0);
    for (int t = blockIdx.x; t < NTILES; t += gridDim.x){
        issue(t + gridDim.x, s ^ 1);
        cpa_wait1();
        __syncthreads();

        const float* sV = buf + s*12288; const float* sM = sV + 8192;
        u64 acc[8][2];
        #pragma unroll
        for (int i = 0; i < 8; ++i){ acc[i][0] = acc[i][1] = 0ull; }

        #pragma unroll 4
        for (int k0 = 0; k0 < 64; k0 += 4){
            u64 vP[4][2];
            #pragma unroll
            for (int kk = 0; kk < 4; ++kk){
                float4 v4 = *(const float4*)(sV + (k0+kk)*128 + (tx<<2));
                vP[kk][0] = pk2(v4.x, v4.y); vP[kk][1] = pk2(v4.z, v4.w);
            }
            #pragma unroll
            for (int i = 0; i < 8; ++i){
                float4 w = *(const float4*)(sM + (ty + (i<<3))*64 + k0);
                fma_bcast(acc[i], w.x, vP[0]); fma_bcast(acc[i], w.y, vP[1]);
                fma_bcast(acc[i], w.z, vP[2]); fma_bcast(acc[i], w.w, vP[3]);
            }
        }
        const int b = t >> 9; const size_t base = (size_t)(t & 511) << 7;
        #pragma unroll
        for (int i = 0; i < 8; ++i){
            const int o = ty + (i<<3);
            float4 r; upk2(acc[i][0], r.x, r.y); upk2(acc[i][1], r.z, r.w);
            *(float4*)(out + ((size_t)(b*64 + o))*HW + base + (tx<<2)) = r;
        }
        __syncthreads();
        s ^= 1;
    }
}

// ---------------- launch ----------------
extern "C" void kernel_launch(void* const* d_in, const int* in_sizes, int n_in,
                              void* d_out, int out_size)
{
    (void)in_sizes; (void)n_in; (void)out_size;
    const float* dg   = (const float*)d_in[0];
    const float* xin  = (const float*)d_in[1];
    const float* yin  = (const float*)d_in[2];
    const float* q1w  = (const float*)d_in[3];
    const float* q2w  = (const float*)d_in[4];
    const float* qdw  = (const float*)d_in[5];
    const float* kvw  = (const float*)d_in[6];
    const float* kvdw = (const float*)d_in[7];
    const float* pjw  = (const float*)d_in[8];
    const float* temp = (const float*)d_in[9];
    float* out = (float*)d_out;

    cudaFuncSetAttribute(k1a_mma, cudaFuncAttributeMaxDynamicSharedMemorySize, 36864);
    cudaFuncSetAttribute(k1b_kv,  cudaFuncAttributeMaxDynamicSharedMemorySize, 98304);
    cudaFuncSetAttribute(k4_out,  cudaFuncAttributeMaxDynamicSharedMemorySize, 98304);

    k0_init<<<32, 256>>>();
    k1a_mma<<<444, 256, 36864>>>(dg, xin, q1w, q2w);
    k1b_kv <<<304, 256, 98304>>>(yin, kvw);
    k2a_dw <<<dim3(16, 192, 8), 256>>>(qdw, kvdw);
    k2b_gram<<<dim3(16, 4, 8), 256>>>();
    k3_attn<<<8, 256>>>(pjw, temp);
    k4_out <<<304, 256, 98304>>>(out);
}